// round 7
// baseline (speedup 1.0000x reference)
#include <cuda_runtime.h>
#include <cuda_bf16.h>
#include <math.h>
#include <stdint.h>

// Problem constants
static constexpr int B_    = 32;
static constexpr int N_    = 2048;
static constexpr int D_    = 128;
static constexpr int HALF_ = 64;
static constexpr float DT_ = 0.01f;
static constexpr int M_ROWS = B_ * N_;   // 65536

// int8 quantization scales
static constexpr float ADJ_Q   = 2048.0f * 127.0f;   // adj in [0,1/2048)
static constexpr float G_Q     = 64.0f;              // g in (-2,2)
static constexpr float T_DESCALE = 1.0f / (ADJ_Q * G_Q);

// Scratch (static device globals)
__device__ float         g_h  [M_ROWS * D_];      // h fp32 [B][N][D]
__device__ __nv_bfloat16 g_hb [M_ROWS * D_];      // bf16 mirror of h
__device__ int8_t        g_adj8[N_ * N_];         // adj s8 (x ADJ_Q)
__device__ int8_t        g_gT8 [N_ * N_];         // gT s8 [b*64+dh][node]
__device__ __nv_bfloat16 g_xh_hi[M_ROWS * 256];   // concat(x,hz) hi
__device__ __nv_bfloat16 g_xh_lo[M_ROWS * 256];   // concat(x,hz) lo
__device__ __nv_bfloat16 g_a_hi [M_ROWS * 256];   // relu hidden hi
__device__ __nv_bfloat16 g_a_lo [M_ROWS * 256];   // relu hidden lo
__device__ __nv_bfloat16 g_WaT_hi[256 * 256], g_WaT_lo[256 * 256];
__device__ __nv_bfloat16 g_WbT_hi[128 * 256], g_WbT_lo[128 * 256];
__device__ __nv_bfloat16 g_W1Tb[64 * 128], g_W2Tb[64 * 128];

__device__ __forceinline__ float4 ld4(const float* p) {
    return *reinterpret_cast<const float4*>(p);
}
__device__ __forceinline__ uint32_t s2u(const void* p) {
    uint32_t r;
    asm("{ .reg .u64 t; cvta.to.shared.u64 t, %1; cvt.u32.u64 %0, t; }"
        : "=r"(r) : "l"(p));
    return r;
}
__device__ __forceinline__ void cp16(uint32_t d, const void* s) {
    asm volatile("cp.async.cg.shared.global [%0], [%1], 16;" :: "r"(d), "l"(s) : "memory");
}
__device__ __forceinline__ uint32_t swz(uint32_t o) { return o ^ ((o >> 3) & 0x70); }
__device__ __forceinline__ float tanh_fast(float x) {
    float y;
    asm("tanh.approx.f32 %0, %1;" : "=f"(y) : "f"(x));
    return y;
}
__device__ __forceinline__ void ldsm4(uint32_t (&r)[4], uint32_t addr) {
    asm volatile("ldmatrix.sync.aligned.m8n8.x4.shared.b16 {%0,%1,%2,%3}, [%4];"
                 : "=r"(r[0]), "=r"(r[1]), "=r"(r[2]), "=r"(r[3]) : "r"(addr));
}
__device__ __forceinline__ void mma16816(float (&c)[4], const uint32_t (&a)[4],
                                         const uint32_t* b) {
    asm volatile(
        "mma.sync.aligned.m16n8k16.row.col.f32.bf16.bf16.f32 "
        "{%0,%1,%2,%3}, {%4,%5,%6,%7}, {%8,%9}, {%0,%1,%2,%3};"
        : "+f"(c[0]), "+f"(c[1]), "+f"(c[2]), "+f"(c[3])
        : "r"(a[0]), "r"(a[1]), "r"(a[2]), "r"(a[3]), "r"(b[0]), "r"(b[1]));
}
__device__ __forceinline__ void mma_s8(int (&c)[4], const uint32_t (&a)[4],
                                       uint32_t b0, uint32_t b1) {
    asm volatile(
        "mma.sync.aligned.m16n8k32.row.col.s32.s8.s8.s32 "
        "{%0,%1,%2,%3}, {%4,%5,%6,%7}, {%8,%9}, {%0,%1,%2,%3};"
        : "+r"(c[0]), "+r"(c[1]), "+r"(c[2]), "+r"(c[3])
        : "r"(a[0]), "r"(a[1]), "r"(a[2]), "r"(a[3]), "r"(b0), "r"(b1));
}
__device__ __forceinline__ int q8(float v) {
    int i = __float2int_rn(v);
    return max(-127, min(127, i));
}
__device__ __forceinline__ void split2(float v, __nv_bfloat16& hi, __nv_bfloat16& lo) {
    hi = __float2bfloat16(v);
    lo = __float2bfloat16(v - __bfloat162float(hi));
}
__device__ __forceinline__ __nv_bfloat162 pack2(__nv_bfloat16 a, __nv_bfloat16 b) {
    __nv_bfloat162 r; r.x = a; r.y = b; return r;
}

// ===========================================================================
// Conversion kernels
// ===========================================================================
__global__ __launch_bounds__(256) void cvt_adj_k(const float* __restrict__ a)
{
    const int i = blockIdx.x * 256 + threadIdx.x;    // one float4 each
    float4 v = ld4(a + (size_t)i * 4);
    const uint32_t w = (uint32_t)(q8(v.x * ADJ_Q) & 0xFF)
                     | ((uint32_t)(q8(v.y * ADJ_Q) & 0xFF) << 8)
                     | ((uint32_t)(q8(v.z * ADJ_Q) & 0xFF) << 16)
                     | ((uint32_t)(q8(v.w * ADJ_Q) & 0xFF) << 24);
    *reinterpret_cast<uint32_t*>(g_adj8 + (size_t)i * 4) = w;
}

__global__ __launch_bounds__(256) void cvt_xh_k(const float* __restrict__ x,
                                                const float* __restrict__ hz)
{
    const int i = blockIdx.x * 256 + threadIdx.x;
    const bool isHz = i >= 2097152;
    const int j = isHz ? i - 2097152 : i;
    const int row = j >> 5;
    const int c4  = (j & 31) * 4;
    float4 v = ld4((isHz ? hz : x) + (size_t)row * 128 + c4);
    __nv_bfloat16 h0, l0, h1, l1, h2, l2, h3, l3;
    split2(v.x, h0, l0); split2(v.y, h1, l1);
    split2(v.z, h2, l2); split2(v.w, h3, l3);
    const size_t o = (size_t)row * 256 + (isHz ? 128 : 0) + c4;
    *reinterpret_cast<__nv_bfloat162*>(g_xh_hi + o)     = pack2(h0, h1);
    *reinterpret_cast<__nv_bfloat162*>(g_xh_hi + o + 2) = pack2(h2, h3);
    *reinterpret_cast<__nv_bfloat162*>(g_xh_lo + o)     = pack2(l0, l1);
    *reinterpret_cast<__nv_bfloat162*>(g_xh_lo + o + 2) = pack2(l2, l3);
}

__global__ __launch_bounds__(256) void cvt_w_k(const float* __restrict__ Wa,
                                               const float* __restrict__ Wb,
                                               const float* __restrict__ W1,
                                               const float* __restrict__ W2)
{
    const int i = blockIdx.x * 256 + threadIdx.x;
    if (i < 65536) {
        const int n = i >> 8, k = i & 255;
        __nv_bfloat16 hi, lo;
        split2(Wa[k * 256 + n], hi, lo);
        g_WaT_hi[i] = hi; g_WaT_lo[i] = lo;
    } else if (i < 65536 + 32768) {
        const int j = i - 65536;
        const int n = j >> 8, k = j & 255;
        __nv_bfloat16 hi, lo;
        split2(Wb[k * 128 + n], hi, lo);
        g_WbT_hi[j] = hi; g_WbT_lo[j] = lo;
    } else if (i < 65536 + 32768 + 8192) {
        const int j = i - 65536 - 32768;
        const int dh = j >> 7, k = j & 127;
        g_W1Tb[j] = __float2bfloat16(W1[k * 128 + dh]);
    } else if (i < 65536 + 32768 + 16384) {
        const int j = i - 65536 - 32768 - 8192;
        const int dh = j >> 7, k = j & 127;
        g_W2Tb[j] = __float2bfloat16(W2[k * 128 + 64 + dh]);
    }
}

// ===========================================================================
// MLP GEMM (bf16x3 split) — unchanged from R4.
// ===========================================================================
static constexpr int MLP_STG_B = 65536;
static constexpr int MLP_SMEM  = 3 * MLP_STG_B;

template <int MODE>
__global__ __launch_bounds__(256, 1) void mlp_mma_k(
    const __nv_bfloat16* __restrict__ Ahi, const __nv_bfloat16* __restrict__ Alo,
    const __nv_bfloat16* __restrict__ Bhi, const __nv_bfloat16* __restrict__ Blo,
    const float* __restrict__ bias)
{
    extern __shared__ char smem[];
    const uint32_t sb = s2u(smem);
    const int tid  = threadIdx.x;
    const int lane = tid & 31;
    const int warp = tid >> 5;
    const int wm   = warp & 1;
    const int wn   = warp >> 1;
    const int bx = blockIdx.x;
    const int by = blockIdx.y;

    float acc[4][4][4];
#pragma unroll
    for (int i = 0; i < 4; i++)
#pragma unroll
        for (int j = 0; j < 4; j++)
#pragma unroll
            for (int v = 0; v < 4; v++) acc[i][j][v] = 0.0f;

    const int ldRow = tid >> 1;
    const int ldCol = (tid & 1) * 4;

    auto issue = [&](int c, int s) {
        const uint32_t st = sb + s * MLP_STG_B;
        const size_t aOff = (size_t)(by * 128 + ldRow) * 256 + c * 64;
        const size_t bOff = (size_t)(bx * 128 + ldRow) * 256 + c * 64;
#pragma unroll
        for (int j = 0; j < 4; j++) {
            const uint32_t so = swz((uint32_t)(ldRow * 128 + (ldCol + j) * 16));
            const int e = (ldCol + j) * 8;
            cp16(st + so,          Ahi + aOff + e);
            cp16(st + 16384 + so,  Alo + aOff + e);
            cp16(st + 32768 + so,  Bhi + bOff + e);
            cp16(st + 49152 + so,  Blo + bOff + e);
        }
    };

    auto compute = [&](int s) {
        const uint32_t st = sb + s * MLP_STG_B;
#pragma unroll
        for (int ks = 0; ks < 4; ks++) {
            const int k0b = ks * 32;
            uint32_t ah[4][4], al[4][4], bh[2][4], bl[2][4];
#pragma unroll
            for (int mt = 0; mt < 4; mt++) {
                const int row = wm * 64 + mt * 16 + (lane & 15);
                const uint32_t o = swz((uint32_t)(row * 128 + k0b + ((lane >> 4) << 4)));
                ldsm4(ah[mt], st + o);
                ldsm4(al[mt], st + 16384 + o);
            }
#pragma unroll
            for (int p = 0; p < 2; p++) {
                const int row = wn * 32 + p * 16 + (lane & 7) + ((lane >> 4) << 3);
                const uint32_t o = swz((uint32_t)(row * 128 + k0b + (((lane >> 3) & 1) << 4)));
                ldsm4(bh[p], st + 32768 + o);
                ldsm4(bl[p], st + 49152 + o);
            }
#pragma unroll
            for (int mt = 0; mt < 4; mt++)
#pragma unroll
                for (int nt = 0; nt < 4; nt++) {
                    const uint32_t* bhp = &bh[nt >> 1][(nt & 1) * 2];
                    const uint32_t* blp = &bl[nt >> 1][(nt & 1) * 2];
                    mma16816(acc[mt][nt], ah[mt], bhp);
                    mma16816(acc[mt][nt], ah[mt], blp);
                    mma16816(acc[mt][nt], al[mt], bhp);
                }
        }
    };

    issue(0, 0);
    asm volatile("cp.async.commit_group;" ::: "memory");
    issue(1, 1);
    asm volatile("cp.async.commit_group;" ::: "memory");
    for (int kt = 0; kt < 4; kt++) {
        asm volatile("cp.async.wait_group 1;" ::: "memory");
        __syncthreads();
        compute(kt % 3);
        if (kt + 2 < 4) issue(kt + 2, (kt + 2) % 3);
        asm volatile("cp.async.commit_group;" ::: "memory");
    }

#pragma unroll
    for (int mt = 0; mt < 4; mt++) {
        const int row0 = by * 128 + wm * 64 + mt * 16 + (lane >> 2);
#pragma unroll
        for (int nt = 0; nt < 4; nt++) {
            const int col = bx * 128 + wn * 32 + nt * 8 + 2 * (lane & 3);
            const float b0 = bias[col], b1 = bias[col + 1];
#pragma unroll
            for (int r = 0; r < 2; r++) {
                const int row = row0 + r * 8;
                float v0 = acc[mt][nt][2 * r + 0] + b0;
                float v1 = acc[mt][nt][2 * r + 1] + b1;
                if (MODE == 1) {
                    v0 = fmaxf(v0, 0.0f);
                    v1 = fmaxf(v1, 0.0f);
                    __nv_bfloat16 h0, l0, h1, l1;
                    split2(v0, h0, l0); split2(v1, h1, l1);
                    const size_t o = (size_t)row * 256 + col;
                    *reinterpret_cast<__nv_bfloat162*>(g_a_hi + o) = pack2(h0, h1);
                    *reinterpret_cast<__nv_bfloat162*>(g_a_lo + o) = pack2(l0, l1);
                } else {
                    v0 = tanhf(v0);
                    v1 = tanhf(v1);
                    const size_t o = (size_t)row * 128 + col;
                    *reinterpret_cast<float2*>(g_h + o) = make_float2(v0, v1);
                    *reinterpret_cast<__nv_bfloat162*>(g_hb + o) =
                        __floats2bfloat162_rn(v0, v1);
                }
            }
        }
    }
}

// ===========================================================================
// gproj (bf16 mma): g = hb @ WTb^T, epilogue emits s8 (x G_Q) transposed.
// CTA 128 rows x 64 cols, K=128.
// ===========================================================================
static constexpr int GP_SMEM = 49152 + 128 * 68;

__global__ __launch_bounds__(256, 1) void gproj_k(
    const __nv_bfloat16* __restrict__ WTb, int8_t* __restrict__ gT8)
{
    extern __shared__ char smem[];
    const uint32_t sb = s2u(smem);
    uint8_t* Ts = reinterpret_cast<uint8_t*>(smem + 49152);
    const int tid  = threadIdx.x;
    const int lane = tid & 31;
    const int warp = tid >> 5;
    const int wm   = warp & 3;
    const int wn   = warp >> 2;
    const int by = blockIdx.y;

    {
        const int r = tid >> 1, half = tid & 1;
        const size_t rowOff = (size_t)(by * 128 + r) * 128;
#pragma unroll
        for (int c = 0; c < 2; c++)
#pragma unroll
            for (int j = 0; j < 4; j++) {
                const uint32_t so = swz((uint32_t)(r * 128 + (half * 4 + j) * 16));
                cp16(sb + c * 16384 + so, g_hb + rowOff + c * 64 + (half * 4 + j) * 8);
            }
    }
    {
        const int r = tid >> 2, q = tid & 3;
#pragma unroll
        for (int c = 0; c < 2; c++)
#pragma unroll
            for (int j = 0; j < 2; j++) {
                const uint32_t so = swz((uint32_t)(r * 128 + (q * 2 + j) * 16));
                cp16(sb + 32768 + c * 8192 + so,
                     WTb + (size_t)r * 128 + c * 64 + (q * 2 + j) * 8);
            }
    }
    asm volatile("cp.async.commit_group;" ::: "memory");
    asm volatile("cp.async.wait_group 0;" ::: "memory");
    __syncthreads();

    float acc[2][4][4];
#pragma unroll
    for (int i = 0; i < 2; i++)
#pragma unroll
        for (int j = 0; j < 4; j++)
#pragma unroll
            for (int v = 0; v < 4; v++) acc[i][j][v] = 0.0f;

#pragma unroll
    for (int c = 0; c < 2; c++) {
        const uint32_t aB = sb + c * 16384;
        const uint32_t bB = sb + 32768 + c * 8192;
#pragma unroll
        for (int ks = 0; ks < 4; ks++) {
            const int k0b = ks * 32;
            uint32_t af[2][4], bf[2][4];
#pragma unroll
            for (int mt = 0; mt < 2; mt++) {
                const int row = wm * 32 + mt * 16 + (lane & 15);
                ldsm4(af[mt], aB + swz((uint32_t)(row * 128 + k0b + ((lane >> 4) << 4))));
            }
#pragma unroll
            for (int p = 0; p < 2; p++) {
                const int row = wn * 32 + p * 16 + (lane & 7) + ((lane >> 4) << 3);
                ldsm4(bf[p], bB + swz((uint32_t)(row * 128 + k0b + (((lane >> 3) & 1) << 4))));
            }
#pragma unroll
            for (int mt = 0; mt < 2; mt++)
#pragma unroll
                for (int nt = 0; nt < 4; nt++)
                    mma16816(acc[mt][nt], af[mt], &bf[nt >> 1][(nt & 1) * 2]);
        }
    }
    __syncthreads();

    // stage s8 bytes then transposed coalesced 16B stores
#pragma unroll
    for (int mt = 0; mt < 2; mt++) {
        const int row0 = wm * 32 + mt * 16 + (lane >> 2);
#pragma unroll
        for (int nt = 0; nt < 4; nt++) {
            const int col = wn * 32 + nt * 8 + 2 * (lane & 3);
#pragma unroll
            for (int r = 0; r < 2; r++) {
                const int row = row0 + r * 8;
                const uint16_t pk =
                    (uint16_t)(q8(acc[mt][nt][2 * r + 0] * G_Q) & 0xFF)
                  | ((uint16_t)(q8(acc[mt][nt][2 * r + 1] * G_Q) & 0xFF) << 8);
                *reinterpret_cast<uint16_t*>(Ts + row * 68 + col) = pk;
            }
        }
    }
    __syncthreads();

    const int colp = tid & 63;
    const int seg  = tid >> 6;
    const int b    = by >> 4;
    const int n0   = (by & 15) * 128;
    int8_t* dst = gT8 + (size_t)(b * 64 + colp) * N_ + n0 + seg * 32;
#pragma unroll
    for (int q = 0; q < 2; q++) {
        const int nd0 = seg * 32 + q * 16;
        uint32_t w[4];
#pragma unroll
        for (int p = 0; p < 4; p++) {
            const int n = nd0 + 4 * p;
            w[p] = (uint32_t)Ts[(n + 0) * 68 + colp]
                 | ((uint32_t)Ts[(n + 1) * 68 + colp] << 8)
                 | ((uint32_t)Ts[(n + 2) * 68 + colp] << 16)
                 | ((uint32_t)Ts[(n + 3) * 68 + colp] << 24);
        }
        *reinterpret_cast<uint4*>(dst + q * 16) = make_uint4(w[0], w[1], w[2], w[3]);
    }
}

// ===========================================================================
// adj GEMM (s8 mma) + fused half-update epilogue.
// CTA 128x128, K-chunk = 128 s8 (128B rows), 4-stage cp.async, 8 warps.
// ===========================================================================
static constexpr int AJ_STAGES  = 4;
static constexpr int AJ_NK      = N_ / 128;        // 16
static constexpr int AJ_TILE    = 16384;
static constexpr int AJ_STAGE_B = 2 * AJ_TILE;
static constexpr int ADJ_SMEM   = AJ_STAGES * AJ_STAGE_B;   // 128 KB

template <int HID>
__global__ __launch_bounds__(256, 1) void adj_mma_k(
    float* __restrict__ out, const float* __restrict__ eps)
{
    extern __shared__ char smem[];
    const uint32_t sb = s2u(smem);
    const int tid  = threadIdx.x;
    const int lane = tid & 31;
    const int warp = tid >> 5;
    const int wm   = warp & 1;
    const int wn   = warp >> 1;
    const int bx = blockIdx.x;
    const int by = blockIdx.y;

    const int8_t* aSrc = g_adj8 + (size_t)(by * 128) * N_;
    const int8_t* bSrc = g_gT8  + (size_t)(bx * 128) * N_;

    int acc[4][4][4];
#pragma unroll
    for (int i = 0; i < 4; i++)
#pragma unroll
        for (int j = 0; j < 4; j++)
#pragma unroll
            for (int v = 0; v < 4; v++) acc[i][j][v] = 0;

    const int ldRow = tid >> 3;
    const int ldCol = tid & 7;

    auto issue = [&](int kt, int s) {
        const uint32_t aB = sb + s * AJ_STAGE_B;
        const uint32_t bB = aB + AJ_TILE;
#pragma unroll
        for (int i = 0; i < 4; i++) {
            const int row = ldRow + 32 * i;
            const uint32_t so = swz((uint32_t)(row * 128 + ldCol * 16));
            const size_t gsrc = (size_t)row * N_ + kt * 128 + ldCol * 16;
            cp16(aB + so, aSrc + gsrc);
            cp16(bB + so, bSrc + gsrc);
        }
    };

    auto compute = [&](int s) {
        const uint32_t aB = sb + s * AJ_STAGE_B;
        const uint32_t bB = aB + AJ_TILE;
#pragma unroll
        for (int ks = 0; ks < 4; ks++) {         // 4 x 32 s8 K
            const int k0b = ks * 32;
            uint32_t af[4][4], bf[2][4];
#pragma unroll
            for (int mt = 0; mt < 4; mt++) {
                const int row = wm * 64 + mt * 16 + (lane & 15);
                ldsm4(af[mt], aB + swz((uint32_t)(row * 128 + k0b + ((lane >> 4) << 4))));
            }
#pragma unroll
            for (int p = 0; p < 2; p++) {
                const int row = wn * 32 + p * 16 + (lane & 7) + ((lane >> 4) << 3);
                ldsm4(bf[p], bB + swz((uint32_t)(row * 128 + k0b + (((lane >> 3) & 1) << 4))));
            }
            // B frag pairing for m16n8k32: (frag0,frag1) = n0-7, (frag2,frag3) = n8-15
#pragma unroll
            for (int mt = 0; mt < 4; mt++)
#pragma unroll
                for (int nt = 0; nt < 4; nt++) {
                    const int p = nt >> 1, sub = nt & 1;
                    mma_s8(acc[mt][nt], af[mt], bf[p][sub * 2], bf[p][sub * 2 + 1]);
                }
        }
    };

#pragma unroll
    for (int s = 0; s < AJ_STAGES - 1; s++) {
        issue(s, s);
        asm volatile("cp.async.commit_group;" ::: "memory");
    }
    for (int kt = 0; kt < AJ_NK; kt++) {
        asm volatile("cp.async.wait_group 2;" ::: "memory");
        __syncthreads();
        compute(kt & 3);
        const int f = kt + AJ_STAGES - 1;
        if (f < AJ_NK) issue(f, f & 3);
        asm volatile("cp.async.commit_group;" ::: "memory");
    }

    // fused epilogue: half-update into h (fp32), hb (bf16), out
#pragma unroll
    for (int mt = 0; mt < 4; mt++) {
        const int node0 = by * 128 + wm * 64 + mt * 16 + (lane >> 2);
#pragma unroll
        for (int nt = 0; nt < 4; nt++) {
            const int col = bx * 128 + wn * 32 + nt * 8 + 2 * (lane & 3);
            const int b  = col >> 6;
            const int dh = col & 63;
#pragma unroll
            for (int r = 0; r < 2; r++) {
                const int node = node0 + r * 8;
                const float t0 = __int2float_rn(acc[mt][nt][2 * r + 0]) * T_DESCALE;
                const float t1 = __int2float_rn(acc[mt][nt][2 * r + 1]) * T_DESCALE;
                const size_t bn = (size_t)b * N_ + node;
                const size_t hi = bn * D_ + HID * HALF_ + dh;
                float2 hv = *reinterpret_cast<const float2*>(g_h + hi);
                if (HID == 0) {
                    hv.x += DT_ * tanh_fast(t0);
                    hv.y += DT_ * tanh_fast(t1);
                } else {
                    float2 ev = *reinterpret_cast<const float2*>(eps + bn * HALF_ + dh);
                    ev.x = fminf(fmaxf(ev.x, 0.0f), 0.1f);
                    ev.y = fminf(fmaxf(ev.y, 0.0f), 0.1f);
                    hv.x = ev.x * (hv.x + DT_ * tanh_fast(t0));
                    hv.y = ev.y * (hv.y + DT_ * tanh_fast(t1));
                }
                *reinterpret_cast<float2*>(g_h + hi) = hv;
                *reinterpret_cast<__nv_bfloat162*>(g_hb + hi) =
                    __floats2bfloat162_rn(hv.x, hv.y);
                *reinterpret_cast<float2*>(out + hi) = hv;
            }
        }
    }
}

// ===========================================================================
extern "C" void kernel_launch(void* const* d_in, const int* /*in_sizes*/,
                              int /*n_in*/, void* d_out, int /*out_size*/)
{
    const float* x   = (const float*)d_in[0];
    const float* hz  = (const float*)d_in[1];
    const float* adj = (const float*)d_in[2];
    const float* W1  = (const float*)d_in[3];
    const float* W2  = (const float*)d_in[4];
    const float* Wa  = (const float*)d_in[5];
    const float* ba  = (const float*)d_in[6];
    const float* Wb  = (const float*)d_in[7];
    const float* bb  = (const float*)d_in[8];
    const float* eps = (const float*)d_in[9];
    float* out = (float*)d_out;

    __nv_bfloat16 *xh_hi, *xh_lo, *WaT_hi, *WaT_lo;
    __nv_bfloat16 *a_hi, *a_lo, *WbT_hi, *WbT_lo;
    __nv_bfloat16 *W1Tb, *W2Tb;
    int8_t *gT8_p;
    cudaGetSymbolAddress((void**)&xh_hi, g_xh_hi);
    cudaGetSymbolAddress((void**)&xh_lo, g_xh_lo);
    cudaGetSymbolAddress((void**)&WaT_hi, g_WaT_hi);
    cudaGetSymbolAddress((void**)&WaT_lo, g_WaT_lo);
    cudaGetSymbolAddress((void**)&a_hi, g_a_hi);
    cudaGetSymbolAddress((void**)&a_lo, g_a_lo);
    cudaGetSymbolAddress((void**)&WbT_hi, g_WbT_hi);
    cudaGetSymbolAddress((void**)&WbT_lo, g_WbT_lo);
    cudaGetSymbolAddress((void**)&W1Tb, g_W1Tb);
    cudaGetSymbolAddress((void**)&W2Tb, g_W2Tb);
    cudaGetSymbolAddress((void**)&gT8_p, g_gT8);

    cudaFuncSetAttribute(mlp_mma_k<1>,
                         cudaFuncAttributeMaxDynamicSharedMemorySize, MLP_SMEM);
    cudaFuncSetAttribute(mlp_mma_k<2>,
                         cudaFuncAttributeMaxDynamicSharedMemorySize, MLP_SMEM);
    cudaFuncSetAttribute(gproj_k,
                         cudaFuncAttributeMaxDynamicSharedMemorySize, GP_SMEM);
    cudaFuncSetAttribute(adj_mma_k<0>,
                         cudaFuncAttributeMaxDynamicSharedMemorySize, ADJ_SMEM);
    cudaFuncSetAttribute(adj_mma_k<1>,
                         cudaFuncAttributeMaxDynamicSharedMemorySize, ADJ_SMEM);

    const dim3 blk(256);
    const dim3 adjGrid(N_ / 128, N_ / 128);

    cvt_adj_k<<<(N_ * N_) / 1024, blk>>>(adj);
    cvt_xh_k<<<16384, blk>>>(x, hz);
    cvt_w_k<<<448, blk>>>(Wa, Wb, W1, W2);

    mlp_mma_k<1><<<dim3(2, M_ROWS / 128), blk, MLP_SMEM>>>(
        xh_hi, xh_lo, WaT_hi, WaT_lo, ba);
    mlp_mma_k<2><<<dim3(1, M_ROWS / 128), blk, MLP_SMEM>>>(
        a_hi, a_lo, WbT_hi, WbT_lo, bb);

    for (int it = 0; it < 2; ++it) {
        gproj_k<<<dim3(1, M_ROWS / 128), blk, GP_SMEM>>>(W1Tb, gT8_p);
        adj_mma_k<0><<<adjGrid, blk, ADJ_SMEM>>>(out, eps);
        gproj_k<<<dim3(1, M_ROWS / 128), blk, GP_SMEM>>>(W2Tb, gT8_p);
        adj_mma_k<1><<<adjGrid, blk, ADJ_SMEM>>>(out, eps);
    }
}

// round 8
// speedup vs baseline: 1.8648x; 1.8648x over previous
#include <cuda_runtime.h>
#include <cuda_bf16.h>
#include <math.h>
#include <stdint.h>

// Problem constants
static constexpr int B_    = 32;
static constexpr int N_    = 2048;
static constexpr int D_    = 128;
static constexpr int HALF_ = 64;
static constexpr float DT_ = 0.01f;
static constexpr int M_ROWS = B_ * N_;   // 65536

// Scratch (static device globals)
__device__ float         g_h  [M_ROWS * D_];      // h fp32 [B][N][D]
__device__ __nv_bfloat16 g_hb [M_ROWS * D_];      // bf16 mirror of h
__device__ __nv_bfloat16 g_adjb[N_ * N_];         // adj bf16
__device__ __nv_bfloat16 g_gT [N_ * N_];          // gT [b*64+dh][node]
__device__ __nv_bfloat16 g_xh_hi[M_ROWS * 256];   // concat(x,hz) hi
__device__ __nv_bfloat16 g_xh_lo[M_ROWS * 256];   // concat(x,hz) lo
__device__ __nv_bfloat16 g_a_hi [M_ROWS * 256];   // relu hidden hi
__device__ __nv_bfloat16 g_a_lo [M_ROWS * 256];   // relu hidden lo
__device__ __nv_bfloat16 g_WaT_hi[256 * 256], g_WaT_lo[256 * 256];
__device__ __nv_bfloat16 g_WbT_hi[128 * 256], g_WbT_lo[128 * 256];
__device__ __nv_bfloat16 g_W1Tb[64 * 128], g_W2Tb[64 * 128];

__device__ __forceinline__ float4 ld4(const float* p) {
    return *reinterpret_cast<const float4*>(p);
}
__device__ __forceinline__ uint32_t s2u(const void* p) {
    uint32_t r;
    asm("{ .reg .u64 t; cvta.to.shared.u64 t, %1; cvt.u32.u64 %0, t; }"
        : "=r"(r) : "l"(p));
    return r;
}
__device__ __forceinline__ void cp16(uint32_t d, const void* s) {
    asm volatile("cp.async.cg.shared.global [%0], [%1], 16;" :: "r"(d), "l"(s) : "memory");
}
__device__ __forceinline__ uint32_t swz(uint32_t o) { return o ^ ((o >> 3) & 0x70); }
__device__ __forceinline__ float tanh_fast(float x) {
    float y;
    asm("tanh.approx.f32 %0, %1;" : "=f"(y) : "f"(x));
    return y;
}
__device__ __forceinline__ void ldsm4(uint32_t (&r)[4], uint32_t addr) {
    asm volatile("ldmatrix.sync.aligned.m8n8.x4.shared.b16 {%0,%1,%2,%3}, [%4];"
                 : "=r"(r[0]), "=r"(r[1]), "=r"(r[2]), "=r"(r[3]) : "r"(addr));
}
__device__ __forceinline__ void mma16816(float (&c)[4], const uint32_t (&a)[4],
                                         const uint32_t* b) {
    asm volatile(
        "mma.sync.aligned.m16n8k16.row.col.f32.bf16.bf16.f32 "
        "{%0,%1,%2,%3}, {%4,%5,%6,%7}, {%8,%9}, {%0,%1,%2,%3};"
        : "+f"(c[0]), "+f"(c[1]), "+f"(c[2]), "+f"(c[3])
        : "r"(a[0]), "r"(a[1]), "r"(a[2]), "r"(a[3]), "r"(b[0]), "r"(b[1]));
}
__device__ __forceinline__ void split2(float v, __nv_bfloat16& hi, __nv_bfloat16& lo) {
    hi = __float2bfloat16(v);
    lo = __float2bfloat16(v - __bfloat162float(hi));
}
__device__ __forceinline__ __nv_bfloat162 pack2(__nv_bfloat16 a, __nv_bfloat16 b) {
    __nv_bfloat162 r; r.x = a; r.y = b; return r;
}

// ===========================================================================
// Conversion kernels
// ===========================================================================
__global__ __launch_bounds__(256) void cvt_adj_k(const float* __restrict__ a)
{
    const int i = blockIdx.x * 256 + threadIdx.x;
    float4 v = ld4(a + (size_t)i * 4);
    *reinterpret_cast<__nv_bfloat162*>(g_adjb + (size_t)i * 4)     =
        __floats2bfloat162_rn(v.x, v.y);
    *reinterpret_cast<__nv_bfloat162*>(g_adjb + (size_t)i * 4 + 2) =
        __floats2bfloat162_rn(v.z, v.w);
}

__global__ __launch_bounds__(256) void cvt_xh_k(const float* __restrict__ x,
                                                const float* __restrict__ hz)
{
    const int i = blockIdx.x * 256 + threadIdx.x;
    const bool isHz = i >= 2097152;
    const int j = isHz ? i - 2097152 : i;
    const int row = j >> 5;
    const int c4  = (j & 31) * 4;
    float4 v = ld4((isHz ? hz : x) + (size_t)row * 128 + c4);
    __nv_bfloat16 h0, l0, h1, l1, h2, l2, h3, l3;
    split2(v.x, h0, l0); split2(v.y, h1, l1);
    split2(v.z, h2, l2); split2(v.w, h3, l3);
    const size_t o = (size_t)row * 256 + (isHz ? 128 : 0) + c4;
    *reinterpret_cast<__nv_bfloat162*>(g_xh_hi + o)     = pack2(h0, h1);
    *reinterpret_cast<__nv_bfloat162*>(g_xh_hi + o + 2) = pack2(h2, h3);
    *reinterpret_cast<__nv_bfloat162*>(g_xh_lo + o)     = pack2(l0, l1);
    *reinterpret_cast<__nv_bfloat162*>(g_xh_lo + o + 2) = pack2(l2, l3);
}

__global__ __launch_bounds__(256) void cvt_w_k(const float* __restrict__ Wa,
                                               const float* __restrict__ Wb,
                                               const float* __restrict__ W1,
                                               const float* __restrict__ W2)
{
    const int i = blockIdx.x * 256 + threadIdx.x;
    if (i < 65536) {
        const int n = i >> 8, k = i & 255;
        __nv_bfloat16 hi, lo;
        split2(Wa[k * 256 + n], hi, lo);
        g_WaT_hi[i] = hi; g_WaT_lo[i] = lo;
    } else if (i < 65536 + 32768) {
        const int j = i - 65536;
        const int n = j >> 8, k = j & 255;
        __nv_bfloat16 hi, lo;
        split2(Wb[k * 128 + n], hi, lo);
        g_WbT_hi[j] = hi; g_WbT_lo[j] = lo;
    } else if (i < 65536 + 32768 + 8192) {
        const int j = i - 65536 - 32768;
        const int dh = j >> 7, k = j & 127;
        g_W1Tb[j] = __float2bfloat16(W1[k * 128 + dh]);
    } else if (i < 65536 + 32768 + 16384) {
        const int j = i - 65536 - 32768 - 8192;
        const int dh = j >> 7, k = j & 127;
        g_W2Tb[j] = __float2bfloat16(W2[k * 128 + 64 + dh]);
    }
}

// ===========================================================================
// MLP GEMM (bf16x3 split) — unchanged from R4.
// ===========================================================================
static constexpr int MLP_STG_B = 65536;
static constexpr int MLP_SMEM  = 3 * MLP_STG_B;

template <int MODE>
__global__ __launch_bounds__(256, 1) void mlp_mma_k(
    const __nv_bfloat16* __restrict__ Ahi, const __nv_bfloat16* __restrict__ Alo,
    const __nv_bfloat16* __restrict__ Bhi, const __nv_bfloat16* __restrict__ Blo,
    const float* __restrict__ bias)
{
    extern __shared__ char smem[];
    const uint32_t sb = s2u(smem);
    const int tid  = threadIdx.x;
    const int lane = tid & 31;
    const int warp = tid >> 5;
    const int wm   = warp & 1;
    const int wn   = warp >> 1;
    const int bx = blockIdx.x;
    const int by = blockIdx.y;

    float acc[4][4][4];
#pragma unroll
    for (int i = 0; i < 4; i++)
#pragma unroll
        for (int j = 0; j < 4; j++)
#pragma unroll
            for (int v = 0; v < 4; v++) acc[i][j][v] = 0.0f;

    const int ldRow = tid >> 1;
    const int ldCol = (tid & 1) * 4;

    auto issue = [&](int c, int s) {
        const uint32_t st = sb + s * MLP_STG_B;
        const size_t aOff = (size_t)(by * 128 + ldRow) * 256 + c * 64;
        const size_t bOff = (size_t)(bx * 128 + ldRow) * 256 + c * 64;
#pragma unroll
        for (int j = 0; j < 4; j++) {
            const uint32_t so = swz((uint32_t)(ldRow * 128 + (ldCol + j) * 16));
            const int e = (ldCol + j) * 8;
            cp16(st + so,          Ahi + aOff + e);
            cp16(st + 16384 + so,  Alo + aOff + e);
            cp16(st + 32768 + so,  Bhi + bOff + e);
            cp16(st + 49152 + so,  Blo + bOff + e);
        }
    };

    auto compute = [&](int s) {
        const uint32_t st = sb + s * MLP_STG_B;
#pragma unroll
        for (int ks = 0; ks < 4; ks++) {
            const int k0b = ks * 32;
            uint32_t ah[4][4], al[4][4], bh[2][4], bl[2][4];
#pragma unroll
            for (int mt = 0; mt < 4; mt++) {
                const int row = wm * 64 + mt * 16 + (lane & 15);
                const uint32_t o = swz((uint32_t)(row * 128 + k0b + ((lane >> 4) << 4)));
                ldsm4(ah[mt], st + o);
                ldsm4(al[mt], st + 16384 + o);
            }
#pragma unroll
            for (int p = 0; p < 2; p++) {
                const int row = wn * 32 + p * 16 + (lane & 7) + ((lane >> 4) << 3);
                const uint32_t o = swz((uint32_t)(row * 128 + k0b + (((lane >> 3) & 1) << 4)));
                ldsm4(bh[p], st + 32768 + o);
                ldsm4(bl[p], st + 49152 + o);
            }
#pragma unroll
            for (int mt = 0; mt < 4; mt++)
#pragma unroll
                for (int nt = 0; nt < 4; nt++) {
                    const uint32_t* bhp = &bh[nt >> 1][(nt & 1) * 2];
                    const uint32_t* blp = &bl[nt >> 1][(nt & 1) * 2];
                    mma16816(acc[mt][nt], ah[mt], bhp);
                    mma16816(acc[mt][nt], ah[mt], blp);
                    mma16816(acc[mt][nt], al[mt], bhp);
                }
        }
    };

    issue(0, 0);
    asm volatile("cp.async.commit_group;" ::: "memory");
    issue(1, 1);
    asm volatile("cp.async.commit_group;" ::: "memory");
    for (int kt = 0; kt < 4; kt++) {
        asm volatile("cp.async.wait_group 1;" ::: "memory");
        __syncthreads();
        compute(kt % 3);
        if (kt + 2 < 4) issue(kt + 2, (kt + 2) % 3);
        asm volatile("cp.async.commit_group;" ::: "memory");
    }

#pragma unroll
    for (int mt = 0; mt < 4; mt++) {
        const int row0 = by * 128 + wm * 64 + mt * 16 + (lane >> 2);
#pragma unroll
        for (int nt = 0; nt < 4; nt++) {
            const int col = bx * 128 + wn * 32 + nt * 8 + 2 * (lane & 3);
            const float b0 = bias[col], b1 = bias[col + 1];
#pragma unroll
            for (int r = 0; r < 2; r++) {
                const int row = row0 + r * 8;
                float v0 = acc[mt][nt][2 * r + 0] + b0;
                float v1 = acc[mt][nt][2 * r + 1] + b1;
                if (MODE == 1) {
                    v0 = fmaxf(v0, 0.0f);
                    v1 = fmaxf(v1, 0.0f);
                    __nv_bfloat16 h0, l0, h1, l1;
                    split2(v0, h0, l0); split2(v1, h1, l1);
                    const size_t o = (size_t)row * 256 + col;
                    *reinterpret_cast<__nv_bfloat162*>(g_a_hi + o) = pack2(h0, h1);
                    *reinterpret_cast<__nv_bfloat162*>(g_a_lo + o) = pack2(l0, l1);
                } else {
                    v0 = tanhf(v0);
                    v1 = tanhf(v1);
                    const size_t o = (size_t)row * 128 + col;
                    *reinterpret_cast<float2*>(g_h + o) = make_float2(v0, v1);
                    *reinterpret_cast<__nv_bfloat162*>(g_hb + o) =
                        __floats2bfloat162_rn(v0, v1);
                }
            }
        }
    }
}

// ===========================================================================
// gproj (bf16 mma): g = hb @ WTb^T, bf16 output transposed into gT.
// CTA 128 rows x 64 cols, K=128.
// ===========================================================================
static constexpr int GP_SMEM = 49152 + 128 * 68 * 2;

__global__ __launch_bounds__(256, 1) void gproj_k(
    const __nv_bfloat16* __restrict__ WTb, __nv_bfloat16* __restrict__ gT)
{
    extern __shared__ char smem[];
    const uint32_t sb = s2u(smem);
    unsigned short* Ts = reinterpret_cast<unsigned short*>(smem + 49152);
    const int tid  = threadIdx.x;
    const int lane = tid & 31;
    const int warp = tid >> 5;
    const int wm   = warp & 3;
    const int wn   = warp >> 2;
    const int by = blockIdx.y;

    {
        const int r = tid >> 1, half = tid & 1;
        const size_t rowOff = (size_t)(by * 128 + r) * 128;
#pragma unroll
        for (int c = 0; c < 2; c++)
#pragma unroll
            for (int j = 0; j < 4; j++) {
                const uint32_t so = swz((uint32_t)(r * 128 + (half * 4 + j) * 16));
                cp16(sb + c * 16384 + so, g_hb + rowOff + c * 64 + (half * 4 + j) * 8);
            }
    }
    {
        const int r = tid >> 2, q = tid & 3;
#pragma unroll
        for (int c = 0; c < 2; c++)
#pragma unroll
            for (int j = 0; j < 2; j++) {
                const uint32_t so = swz((uint32_t)(r * 128 + (q * 2 + j) * 16));
                cp16(sb + 32768 + c * 8192 + so,
                     WTb + (size_t)r * 128 + c * 64 + (q * 2 + j) * 8);
            }
    }
    asm volatile("cp.async.commit_group;" ::: "memory");
    asm volatile("cp.async.wait_group 0;" ::: "memory");
    __syncthreads();

    float acc[2][4][4];
#pragma unroll
    for (int i = 0; i < 2; i++)
#pragma unroll
        for (int j = 0; j < 4; j++)
#pragma unroll
            for (int v = 0; v < 4; v++) acc[i][j][v] = 0.0f;

#pragma unroll
    for (int c = 0; c < 2; c++) {
        const uint32_t aB = sb + c * 16384;
        const uint32_t bB = sb + 32768 + c * 8192;
#pragma unroll
        for (int ks = 0; ks < 4; ks++) {
            const int k0b = ks * 32;
            uint32_t af[2][4], bf[2][4];
#pragma unroll
            for (int mt = 0; mt < 2; mt++) {
                const int row = wm * 32 + mt * 16 + (lane & 15);
                ldsm4(af[mt], aB + swz((uint32_t)(row * 128 + k0b + ((lane >> 4) << 4))));
            }
#pragma unroll
            for (int p = 0; p < 2; p++) {
                const int row = wn * 32 + p * 16 + (lane & 7) + ((lane >> 4) << 3);
                ldsm4(bf[p], bB + swz((uint32_t)(row * 128 + k0b + (((lane >> 3) & 1) << 4))));
            }
#pragma unroll
            for (int mt = 0; mt < 2; mt++)
#pragma unroll
                for (int nt = 0; nt < 4; nt++)
                    mma16816(acc[mt][nt], af[mt], &bf[nt >> 1][(nt & 1) * 2]);
        }
    }
    __syncthreads();

#pragma unroll
    for (int mt = 0; mt < 2; mt++) {
        const int row0 = wm * 32 + mt * 16 + (lane >> 2);
#pragma unroll
        for (int nt = 0; nt < 4; nt++) {
            const int col = wn * 32 + nt * 8 + 2 * (lane & 3);
#pragma unroll
            for (int r = 0; r < 2; r++) {
                const int row = row0 + r * 8;
                __nv_bfloat16 b0 = __float2bfloat16(acc[mt][nt][2 * r + 0]);
                __nv_bfloat16 b1 = __float2bfloat16(acc[mt][nt][2 * r + 1]);
                Ts[row * 68 + col]     = *reinterpret_cast<unsigned short*>(&b0);
                Ts[row * 68 + col + 1] = *reinterpret_cast<unsigned short*>(&b1);
            }
        }
    }
    __syncthreads();

    const int colp = tid & 63;
    const int seg  = tid >> 6;
    const int b    = by >> 4;
    const int n0   = (by & 15) * 128;
    __nv_bfloat16* dst = gT + (size_t)(b * 64 + colp) * N_ + n0 + seg * 32;
#pragma unroll
    for (int q = 0; q < 4; q++) {
        const int r0 = seg * 32 + q * 8;
        uint32_t w[4];
#pragma unroll
        for (int p = 0; p < 4; p++) {
            uint32_t lo = Ts[(r0 + 2 * p) * 68 + colp];
            uint32_t hi = Ts[(r0 + 2 * p + 1) * 68 + colp];
            w[p] = lo | (hi << 16);
        }
        *reinterpret_cast<uint4*>(dst + q * 8) = make_uint4(w[0], w[1], w[2], w[3]);
    }
}

// ===========================================================================
// adj GEMM (bf16 mma) + fused half-update epilogue.
// CTA 128x128, BK=64 bf16 (128B rows), 3-stage cp.async (96 KB smem),
// __launch_bounds__(256, 2) -> 2 CTAs/SM for latency hiding.
// ===========================================================================
static constexpr int AJ_STAGES  = 3;
static constexpr int AJ_NK      = N_ / 64;         // 32
static constexpr int AJ_TILE    = 16384;           // 128 rows x 128B
static constexpr int AJ_STAGE_B = 2 * AJ_TILE;
static constexpr int ADJ_SMEM   = AJ_STAGES * AJ_STAGE_B;   // 96 KB

template <int HID>
__global__ __launch_bounds__(256, 2) void adj_mma_k(
    float* __restrict__ out, const float* __restrict__ eps)
{
    extern __shared__ char smem[];
    const uint32_t sb = s2u(smem);
    const int tid  = threadIdx.x;
    const int lane = tid & 31;
    const int warp = tid >> 5;
    const int wm   = warp & 1;
    const int wn   = warp >> 1;
    const int bx = blockIdx.x;
    const int by = blockIdx.y;

    const char* aSrc = (const char*)(g_adjb + (size_t)(by * 128) * N_);
    const char* bSrc = (const char*)(g_gT   + (size_t)(bx * 128) * N_);

    float acc[4][4][4];
#pragma unroll
    for (int i = 0; i < 4; i++)
#pragma unroll
        for (int j = 0; j < 4; j++)
#pragma unroll
            for (int v = 0; v < 4; v++) acc[i][j][v] = 0.0f;

    const int ldRow = tid >> 3;
    const int ldCol = tid & 7;

    auto issue = [&](int kt, int s) {
        const uint32_t aB = sb + s * AJ_STAGE_B;
        const uint32_t bB = aB + AJ_TILE;
#pragma unroll
        for (int i = 0; i < 4; i++) {
            const int row = ldRow + 32 * i;
            const uint32_t so = swz((uint32_t)(row * 128 + ldCol * 16));
            const size_t gsrc = (size_t)row * (N_ * 2) + kt * 128 + ldCol * 16;
            cp16(aB + so, aSrc + gsrc);
            cp16(bB + so, bSrc + gsrc);
        }
    };

    auto compute = [&](int s) {
        const uint32_t aB = sb + s * AJ_STAGE_B;
        const uint32_t bB = aB + AJ_TILE;
#pragma unroll
        for (int ks = 0; ks < 4; ks++) {
            const int k0b = ks * 32;
            uint32_t af[4][4], bf[2][4];
#pragma unroll
            for (int mt = 0; mt < 4; mt++) {
                const int row = wm * 64 + mt * 16 + (lane & 15);
                ldsm4(af[mt], aB + swz((uint32_t)(row * 128 + k0b + ((lane >> 4) << 4))));
            }
#pragma unroll
            for (int p = 0; p < 2; p++) {
                const int row = wn * 32 + p * 16 + (lane & 7) + ((lane >> 4) << 3);
                ldsm4(bf[p], bB + swz((uint32_t)(row * 128 + k0b + (((lane >> 3) & 1) << 4))));
            }
#pragma unroll
            for (int mt = 0; mt < 4; mt++)
#pragma unroll
                for (int nt = 0; nt < 4; nt++)
                    mma16816(acc[mt][nt], af[mt], &bf[nt >> 1][(nt & 1) * 2]);
        }
    };

    issue(0, 0);
    asm volatile("cp.async.commit_group;" ::: "memory");
    issue(1, 1);
    asm volatile("cp.async.commit_group;" ::: "memory");
    for (int kt = 0; kt < AJ_NK; kt++) {
        asm volatile("cp.async.wait_group 1;" ::: "memory");
        __syncthreads();
        compute(kt % 3);
        const int f = kt + 2;
        if (f < AJ_NK) issue(f, f % 3);
        asm volatile("cp.async.commit_group;" ::: "memory");
    }

    // fused epilogue: half-update into h (fp32), hb (bf16), out
#pragma unroll
    for (int mt = 0; mt < 4; mt++) {
        const int node0 = by * 128 + wm * 64 + mt * 16 + (lane >> 2);
#pragma unroll
        for (int nt = 0; nt < 4; nt++) {
            const int col = bx * 128 + wn * 32 + nt * 8 + 2 * (lane & 3);
            const int b  = col >> 6;
            const int dh = col & 63;
#pragma unroll
            for (int r = 0; r < 2; r++) {
                const int node = node0 + r * 8;
                const float t0 = acc[mt][nt][2 * r + 0];
                const float t1 = acc[mt][nt][2 * r + 1];
                const size_t bn = (size_t)b * N_ + node;
                const size_t hi = bn * D_ + HID * HALF_ + dh;
                float2 hv = *reinterpret_cast<const float2*>(g_h + hi);
                if (HID == 0) {
                    hv.x += DT_ * tanh_fast(t0);
                    hv.y += DT_ * tanh_fast(t1);
                } else {
                    float2 ev = *reinterpret_cast<const float2*>(eps + bn * HALF_ + dh);
                    ev.x = fminf(fmaxf(ev.x, 0.0f), 0.1f);
                    ev.y = fminf(fmaxf(ev.y, 0.0f), 0.1f);
                    hv.x = ev.x * (hv.x + DT_ * tanh_fast(t0));
                    hv.y = ev.y * (hv.y + DT_ * tanh_fast(t1));
                }
                *reinterpret_cast<float2*>(g_h + hi) = hv;
                *reinterpret_cast<__nv_bfloat162*>(g_hb + hi) =
                    __floats2bfloat162_rn(hv.x, hv.y);
                *reinterpret_cast<float2*>(out + hi) = hv;
            }
        }
    }
}

// ===========================================================================
extern "C" void kernel_launch(void* const* d_in, const int* /*in_sizes*/,
                              int /*n_in*/, void* d_out, int /*out_size*/)
{
    const float* x   = (const float*)d_in[0];
    const float* hz  = (const float*)d_in[1];
    const float* adj = (const float*)d_in[2];
    const float* W1  = (const float*)d_in[3];
    const float* W2  = (const float*)d_in[4];
    const float* Wa  = (const float*)d_in[5];
    const float* ba  = (const float*)d_in[6];
    const float* Wb  = (const float*)d_in[7];
    const float* bb  = (const float*)d_in[8];
    const float* eps = (const float*)d_in[9];
    float* out = (float*)d_out;

    __nv_bfloat16 *xh_hi, *xh_lo, *WaT_hi, *WaT_lo;
    __nv_bfloat16 *a_hi, *a_lo, *WbT_hi, *WbT_lo;
    __nv_bfloat16 *W1Tb, *W2Tb, *gT_p;
    cudaGetSymbolAddress((void**)&xh_hi, g_xh_hi);
    cudaGetSymbolAddress((void**)&xh_lo, g_xh_lo);
    cudaGetSymbolAddress((void**)&WaT_hi, g_WaT_hi);
    cudaGetSymbolAddress((void**)&WaT_lo, g_WaT_lo);
    cudaGetSymbolAddress((void**)&a_hi, g_a_hi);
    cudaGetSymbolAddress((void**)&a_lo, g_a_lo);
    cudaGetSymbolAddress((void**)&WbT_hi, g_WbT_hi);
    cudaGetSymbolAddress((void**)&WbT_lo, g_WbT_lo);
    cudaGetSymbolAddress((void**)&W1Tb, g_W1Tb);
    cudaGetSymbolAddress((void**)&W2Tb, g_W2Tb);
    cudaGetSymbolAddress((void**)&gT_p, g_gT);

    cudaFuncSetAttribute(mlp_mma_k<1>,
                         cudaFuncAttributeMaxDynamicSharedMemorySize, MLP_SMEM);
    cudaFuncSetAttribute(mlp_mma_k<2>,
                         cudaFuncAttributeMaxDynamicSharedMemorySize, MLP_SMEM);
    cudaFuncSetAttribute(gproj_k,
                         cudaFuncAttributeMaxDynamicSharedMemorySize, GP_SMEM);
    cudaFuncSetAttribute(adj_mma_k<0>,
                         cudaFuncAttributeMaxDynamicSharedMemorySize, ADJ_SMEM);
    cudaFuncSetAttribute(adj_mma_k<1>,
                         cudaFuncAttributeMaxDynamicSharedMemorySize, ADJ_SMEM);

    const dim3 blk(256);
    const dim3 adjGrid(N_ / 128, N_ / 128);

    cvt_adj_k<<<(N_ * N_) / 1024, blk>>>(adj);
    cvt_xh_k<<<16384, blk>>>(x, hz);
    cvt_w_k<<<448, blk>>>(Wa, Wb, W1, W2);

    mlp_mma_k<1><<<dim3(2, M_ROWS / 128), blk, MLP_SMEM>>>(
        xh_hi, xh_lo, WaT_hi, WaT_lo, ba);
    mlp_mma_k<2><<<dim3(1, M_ROWS / 128), blk, MLP_SMEM>>>(
        a_hi, a_lo, WbT_hi, WbT_lo, bb);

    for (int it = 0; it < 2; ++it) {
        gproj_k<<<dim3(1, M_ROWS / 128), blk, GP_SMEM>>>(W1Tb, gT_p);
        adj_mma_k<0><<<adjGrid, blk, ADJ_SMEM>>>(out, eps);
        gproj_k<<<dim3(1, M_ROWS / 128), blk, GP_SMEM>>>(W2Tb, gT_p);
        adj_mma_k<1><<<adjGrid, blk, ADJ_SMEM>>>(out, eps);
    }
}

// round 9
// speedup vs baseline: 1.9628x; 1.0526x over previous
#include <cuda_runtime.h>
#include <cuda_bf16.h>
#include <math.h>
#include <stdint.h>

// Problem constants
static constexpr int B_    = 32;
static constexpr int N_    = 2048;
static constexpr int D_    = 128;
static constexpr int HALF_ = 64;
static constexpr float DT_ = 0.01f;
static constexpr int M_ROWS = B_ * N_;   // 65536

// Scratch (static device globals)
__device__ float         g_h  [M_ROWS * D_];      // h fp32 [B][N][D]
__device__ __nv_bfloat16 g_hb [M_ROWS * D_];      // bf16 mirror of h
__device__ __nv_bfloat16 g_adjb[N_ * N_];         // adj bf16
__device__ __nv_bfloat16 g_gT [N_ * N_];          // gT [b*64+dh][node]
__device__ __nv_bfloat16 g_xh_hi[M_ROWS * 256];   // concat(x,hz) hi
__device__ __nv_bfloat16 g_xh_lo[M_ROWS * 256];   // concat(x,hz) lo
__device__ __nv_bfloat16 g_a_hi [M_ROWS * 256];   // relu hidden hi
__device__ __nv_bfloat16 g_a_lo [M_ROWS * 256];   // relu hidden lo
__device__ __nv_bfloat16 g_WaT_hi[256 * 256], g_WaT_lo[256 * 256];
__device__ __nv_bfloat16 g_WbT_hi[128 * 256], g_WbT_lo[128 * 256];
__device__ __nv_bfloat16 g_W1Tb[64 * 128], g_W2Tb[64 * 128];

__device__ __forceinline__ float4 ld4(const float* p) {
    return *reinterpret_cast<const float4*>(p);
}
__device__ __forceinline__ uint32_t s2u(const void* p) {
    uint32_t r;
    asm("{ .reg .u64 t; cvta.to.shared.u64 t, %1; cvt.u32.u64 %0, t; }"
        : "=r"(r) : "l"(p));
    return r;
}
__device__ __forceinline__ void cp16(uint32_t d, const void* s) {
    asm volatile("cp.async.cg.shared.global [%0], [%1], 16;" :: "r"(d), "l"(s) : "memory");
}
__device__ __forceinline__ uint32_t swz(uint32_t o)   { return o ^ ((o >> 3) & 0x70); }
__device__ __forceinline__ uint32_t swz64(uint32_t o) { return o ^ ((o >> 3) & 0x30); }
__device__ __forceinline__ float tanh_fast(float x) {
    float y;
    asm("tanh.approx.f32 %0, %1;" : "=f"(y) : "f"(x));
    return y;
}
__device__ __forceinline__ void ldsm4(uint32_t (&r)[4], uint32_t addr) {
    asm volatile("ldmatrix.sync.aligned.m8n8.x4.shared.b16 {%0,%1,%2,%3}, [%4];"
                 : "=r"(r[0]), "=r"(r[1]), "=r"(r[2]), "=r"(r[3]) : "r"(addr));
}
__device__ __forceinline__ void mma16816(float (&c)[4], const uint32_t (&a)[4],
                                         const uint32_t* b) {
    asm volatile(
        "mma.sync.aligned.m16n8k16.row.col.f32.bf16.bf16.f32 "
        "{%0,%1,%2,%3}, {%4,%5,%6,%7}, {%8,%9}, {%0,%1,%2,%3};"
        : "+f"(c[0]), "+f"(c[1]), "+f"(c[2]), "+f"(c[3])
        : "r"(a[0]), "r"(a[1]), "r"(a[2]), "r"(a[3]), "r"(b[0]), "r"(b[1]));
}
__device__ __forceinline__ void split2(float v, __nv_bfloat16& hi, __nv_bfloat16& lo) {
    hi = __float2bfloat16(v);
    lo = __float2bfloat16(v - __bfloat162float(hi));
}
__device__ __forceinline__ __nv_bfloat162 pack2(__nv_bfloat16 a, __nv_bfloat16 b) {
    __nv_bfloat162 r; r.x = a; r.y = b; return r;
}

// ===========================================================================
// Conversion kernels
// ===========================================================================
__global__ __launch_bounds__(256) void cvt_adj_k(const float* __restrict__ a)
{
    const int i = blockIdx.x * 256 + threadIdx.x;
    float4 v = ld4(a + (size_t)i * 4);
    *reinterpret_cast<__nv_bfloat162*>(g_adjb + (size_t)i * 4)     =
        __floats2bfloat162_rn(v.x, v.y);
    *reinterpret_cast<__nv_bfloat162*>(g_adjb + (size_t)i * 4 + 2) =
        __floats2bfloat162_rn(v.z, v.w);
}

__global__ __launch_bounds__(256) void cvt_xh_k(const float* __restrict__ x,
                                                const float* __restrict__ hz)
{
    const int i = blockIdx.x * 256 + threadIdx.x;
    const bool isHz = i >= 2097152;
    const int j = isHz ? i - 2097152 : i;
    const int row = j >> 5;
    const int c4  = (j & 31) * 4;
    float4 v = ld4((isHz ? hz : x) + (size_t)row * 128 + c4);
    __nv_bfloat16 h0, l0, h1, l1, h2, l2, h3, l3;
    split2(v.x, h0, l0); split2(v.y, h1, l1);
    split2(v.z, h2, l2); split2(v.w, h3, l3);
    const size_t o = (size_t)row * 256 + (isHz ? 128 : 0) + c4;
    *reinterpret_cast<__nv_bfloat162*>(g_xh_hi + o)     = pack2(h0, h1);
    *reinterpret_cast<__nv_bfloat162*>(g_xh_hi + o + 2) = pack2(h2, h3);
    *reinterpret_cast<__nv_bfloat162*>(g_xh_lo + o)     = pack2(l0, l1);
    *reinterpret_cast<__nv_bfloat162*>(g_xh_lo + o + 2) = pack2(l2, l3);
}

__global__ __launch_bounds__(256) void cvt_w_k(const float* __restrict__ Wa,
                                               const float* __restrict__ Wb,
                                               const float* __restrict__ W1,
                                               const float* __restrict__ W2)
{
    const int i = blockIdx.x * 256 + threadIdx.x;
    if (i < 65536) {
        const int n = i >> 8, k = i & 255;
        __nv_bfloat16 hi, lo;
        split2(Wa[k * 256 + n], hi, lo);
        g_WaT_hi[i] = hi; g_WaT_lo[i] = lo;
    } else if (i < 65536 + 32768) {
        const int j = i - 65536;
        const int n = j >> 8, k = j & 255;
        __nv_bfloat16 hi, lo;
        split2(Wb[k * 128 + n], hi, lo);
        g_WbT_hi[j] = hi; g_WbT_lo[j] = lo;
    } else if (i < 65536 + 32768 + 8192) {
        const int j = i - 65536 - 32768;
        const int dh = j >> 7, k = j & 127;
        g_W1Tb[j] = __float2bfloat16(W1[k * 128 + dh]);
    } else if (i < 65536 + 32768 + 16384) {
        const int j = i - 65536 - 32768 - 8192;
        const int dh = j >> 7, k = j & 127;
        g_W2Tb[j] = __float2bfloat16(W2[k * 128 + 64 + dh]);
    }
}

// ===========================================================================
// MLP GEMM (bf16x3 split): C = act(A @ W^T + bias)
// CTA 128x128, K=256 in 8 chunks of 32 (64B rows, SW64 swizzle),
// 3-stage cp.async (stage = 4 x 8KB = 32KB -> 96KB total),
// __launch_bounds__(256, 2) -> 2 CTAs/SM.
// ===========================================================================
static constexpr int MLP_STG_B = 32768;
static constexpr int MLP_SMEM  = 3 * MLP_STG_B;   // 98304
static constexpr int MLP_NK    = 8;               // 256 / 32

template <int MODE>
__global__ __launch_bounds__(256, 2) void mlp_mma_k(
    const __nv_bfloat16* __restrict__ Ahi, const __nv_bfloat16* __restrict__ Alo,
    const __nv_bfloat16* __restrict__ Bhi, const __nv_bfloat16* __restrict__ Blo,
    const float* __restrict__ bias)
{
    extern __shared__ char smem[];
    const uint32_t sb = s2u(smem);
    const int tid  = threadIdx.x;
    const int lane = tid & 31;
    const int warp = tid >> 5;
    const int wm   = warp & 1;       // 2 warps M (64 each)
    const int wn   = warp >> 1;      // 4 warps N (32 each)
    const int bx = blockIdx.x;
    const int by = blockIdx.y;

    float acc[4][4][4];
#pragma unroll
    for (int i = 0; i < 4; i++)
#pragma unroll
        for (int j = 0; j < 4; j++)
#pragma unroll
            for (int v = 0; v < 4; v++) acc[i][j][v] = 0.0f;

    const int ldRow  = tid >> 1;         // 0..127
    const int ldHalf = tid & 1;          // 2 x 16B chunks each

    auto issue = [&](int c, int s) {
        const uint32_t st = sb + s * MLP_STG_B;
        const size_t aOff = (size_t)(by * 128 + ldRow) * 256 + c * 32;
        const size_t bOff = (size_t)(bx * 128 + ldRow) * 256 + c * 32;
#pragma unroll
        for (int j = 0; j < 2; j++) {
            const int chunk = ldHalf * 2 + j;
            const uint32_t so = swz64((uint32_t)(ldRow * 64 + chunk * 16));
            const int e = chunk * 8;
            cp16(st + so,          Ahi + aOff + e);
            cp16(st + 8192 + so,   Alo + aOff + e);
            cp16(st + 16384 + so,  Bhi + bOff + e);
            cp16(st + 24576 + so,  Blo + bOff + e);
        }
    };

    auto compute = [&](int s) {
        const uint32_t st = sb + s * MLP_STG_B;
#pragma unroll
        for (int ks = 0; ks < 2; ks++) {
            const int k0b = ks * 32;
            uint32_t ah[4][4], al[4][4], bh[2][4], bl[2][4];
#pragma unroll
            for (int mt = 0; mt < 4; mt++) {
                const int row = wm * 64 + mt * 16 + (lane & 15);
                const uint32_t o = swz64((uint32_t)(row * 64 + k0b + ((lane >> 4) << 4)));
                ldsm4(ah[mt], st + o);
                ldsm4(al[mt], st + 8192 + o);
            }
#pragma unroll
            for (int p = 0; p < 2; p++) {
                const int row = wn * 32 + p * 16 + (lane & 7) + ((lane >> 4) << 3);
                const uint32_t o = swz64((uint32_t)(row * 64 + k0b + (((lane >> 3) & 1) << 4)));
                ldsm4(bh[p], st + 16384 + o);
                ldsm4(bl[p], st + 24576 + o);
            }
#pragma unroll
            for (int mt = 0; mt < 4; mt++)
#pragma unroll
                for (int nt = 0; nt < 4; nt++) {
                    const uint32_t* bhp = &bh[nt >> 1][(nt & 1) * 2];
                    const uint32_t* blp = &bl[nt >> 1][(nt & 1) * 2];
                    mma16816(acc[mt][nt], ah[mt], bhp);
                    mma16816(acc[mt][nt], ah[mt], blp);
                    mma16816(acc[mt][nt], al[mt], bhp);
                }
        }
    };

    issue(0, 0);
    asm volatile("cp.async.commit_group;" ::: "memory");
    issue(1, 1);
    asm volatile("cp.async.commit_group;" ::: "memory");
    for (int kt = 0; kt < MLP_NK; kt++) {
        asm volatile("cp.async.wait_group 1;" ::: "memory");
        __syncthreads();
        compute(kt % 3);
        if (kt + 2 < MLP_NK) issue(kt + 2, (kt + 2) % 3);
        asm volatile("cp.async.commit_group;" ::: "memory");
    }

#pragma unroll
    for (int mt = 0; mt < 4; mt++) {
        const int row0 = by * 128 + wm * 64 + mt * 16 + (lane >> 2);
#pragma unroll
        for (int nt = 0; nt < 4; nt++) {
            const int col = bx * 128 + wn * 32 + nt * 8 + 2 * (lane & 3);
            const float b0 = bias[col], b1 = bias[col + 1];
#pragma unroll
            for (int r = 0; r < 2; r++) {
                const int row = row0 + r * 8;
                float v0 = acc[mt][nt][2 * r + 0] + b0;
                float v1 = acc[mt][nt][2 * r + 1] + b1;
                if (MODE == 1) {
                    v0 = fmaxf(v0, 0.0f);
                    v1 = fmaxf(v1, 0.0f);
                    __nv_bfloat16 h0, l0, h1, l1;
                    split2(v0, h0, l0); split2(v1, h1, l1);
                    const size_t o = (size_t)row * 256 + col;
                    *reinterpret_cast<__nv_bfloat162*>(g_a_hi + o) = pack2(h0, h1);
                    *reinterpret_cast<__nv_bfloat162*>(g_a_lo + o) = pack2(l0, l1);
                } else {
                    v0 = tanhf(v0);
                    v1 = tanhf(v1);
                    const size_t o = (size_t)row * 128 + col;
                    *reinterpret_cast<float2*>(g_h + o) = make_float2(v0, v1);
                    *reinterpret_cast<__nv_bfloat162*>(g_hb + o) =
                        __floats2bfloat162_rn(v0, v1);
                }
            }
        }
    }
}

// ===========================================================================
// gproj (bf16 mma): g = hb @ WTb^T, bf16 output transposed into gT.
// CTA 128 rows x 64 cols, K=128. 2 CTAs/SM.
// ===========================================================================
static constexpr int GP_SMEM = 49152 + 128 * 68 * 2;

__global__ __launch_bounds__(256, 2) void gproj_k(
    const __nv_bfloat16* __restrict__ WTb, __nv_bfloat16* __restrict__ gT)
{
    extern __shared__ char smem[];
    const uint32_t sb = s2u(smem);
    unsigned short* Ts = reinterpret_cast<unsigned short*>(smem + 49152);
    const int tid  = threadIdx.x;
    const int lane = tid & 31;
    const int warp = tid >> 5;
    const int wm   = warp & 3;
    const int wn   = warp >> 2;
    const int by = blockIdx.y;

    {
        const int r = tid >> 1, half = tid & 1;
        const size_t rowOff = (size_t)(by * 128 + r) * 128;
#pragma unroll
        for (int c = 0; c < 2; c++)
#pragma unroll
            for (int j = 0; j < 4; j++) {
                const uint32_t so = swz((uint32_t)(r * 128 + (half * 4 + j) * 16));
                cp16(sb + c * 16384 + so, g_hb + rowOff + c * 64 + (half * 4 + j) * 8);
            }
    }
    {
        const int r = tid >> 2, q = tid & 3;
#pragma unroll
        for (int c = 0; c < 2; c++)
#pragma unroll
            for (int j = 0; j < 2; j++) {
                const uint32_t so = swz((uint32_t)(r * 128 + (q * 2 + j) * 16));
                cp16(sb + 32768 + c * 8192 + so,
                     WTb + (size_t)r * 128 + c * 64 + (q * 2 + j) * 8);
            }
    }
    asm volatile("cp.async.commit_group;" ::: "memory");
    asm volatile("cp.async.wait_group 0;" ::: "memory");
    __syncthreads();

    float acc[2][4][4];
#pragma unroll
    for (int i = 0; i < 2; i++)
#pragma unroll
        for (int j = 0; j < 4; j++)
#pragma unroll
            for (int v = 0; v < 4; v++) acc[i][j][v] = 0.0f;

#pragma unroll
    for (int c = 0; c < 2; c++) {
        const uint32_t aB = sb + c * 16384;
        const uint32_t bB = sb + 32768 + c * 8192;
#pragma unroll
        for (int ks = 0; ks < 4; ks++) {
            const int k0b = ks * 32;
            uint32_t af[2][4], bf[2][4];
#pragma unroll
            for (int mt = 0; mt < 2; mt++) {
                const int row = wm * 32 + mt * 16 + (lane & 15);
                ldsm4(af[mt], aB + swz((uint32_t)(row * 128 + k0b + ((lane >> 4) << 4))));
            }
#pragma unroll
            for (int p = 0; p < 2; p++) {
                const int row = wn * 32 + p * 16 + (lane & 7) + ((lane >> 4) << 3);
                ldsm4(bf[p], bB + swz((uint32_t)(row * 128 + k0b + (((lane >> 3) & 1) << 4))));
            }
#pragma unroll
            for (int mt = 0; mt < 2; mt++)
#pragma unroll
                for (int nt = 0; nt < 4; nt++)
                    mma16816(acc[mt][nt], af[mt], &bf[nt >> 1][(nt & 1) * 2]);
        }
    }
    __syncthreads();

#pragma unroll
    for (int mt = 0; mt < 2; mt++) {
        const int row0 = wm * 32 + mt * 16 + (lane >> 2);
#pragma unroll
        for (int nt = 0; nt < 4; nt++) {
            const int col = wn * 32 + nt * 8 + 2 * (lane & 3);
#pragma unroll
            for (int r = 0; r < 2; r++) {
                const int row = row0 + r * 8;
                __nv_bfloat16 b0 = __float2bfloat16(acc[mt][nt][2 * r + 0]);
                __nv_bfloat16 b1 = __float2bfloat16(acc[mt][nt][2 * r + 1]);
                Ts[row * 68 + col]     = *reinterpret_cast<unsigned short*>(&b0);
                Ts[row * 68 + col + 1] = *reinterpret_cast<unsigned short*>(&b1);
            }
        }
    }
    __syncthreads();

    const int colp = tid & 63;
    const int seg  = tid >> 6;
    const int b    = by >> 4;
    const int n0   = (by & 15) * 128;
    __nv_bfloat16* dst = gT + (size_t)(b * 64 + colp) * N_ + n0 + seg * 32;
#pragma unroll
    for (int q = 0; q < 4; q++) {
        const int r0 = seg * 32 + q * 8;
        uint32_t w[4];
#pragma unroll
        for (int p = 0; p < 4; p++) {
            uint32_t lo = Ts[(r0 + 2 * p) * 68 + colp];
            uint32_t hi = Ts[(r0 + 2 * p + 1) * 68 + colp];
            w[p] = lo | (hi << 16);
        }
        *reinterpret_cast<uint4*>(dst + q * 8) = make_uint4(w[0], w[1], w[2], w[3]);
    }
}

// ===========================================================================
// adj GEMM (bf16 mma) + fused half-update epilogue. (R8, unchanged)
// CTA 128x128, BK=64, 3-stage cp.async (96 KB), 2 CTAs/SM.
// ===========================================================================
static constexpr int AJ_STAGES  = 3;
static constexpr int AJ_NK      = N_ / 64;         // 32
static constexpr int AJ_TILE    = 16384;
static constexpr int AJ_STAGE_B = 2 * AJ_TILE;
static constexpr int ADJ_SMEM   = AJ_STAGES * AJ_STAGE_B;   // 96 KB

template <int HID>
__global__ __launch_bounds__(256, 2) void adj_mma_k(
    float* __restrict__ out, const float* __restrict__ eps)
{
    extern __shared__ char smem[];
    const uint32_t sb = s2u(smem);
    const int tid  = threadIdx.x;
    const int lane = tid & 31;
    const int warp = tid >> 5;
    const int wm   = warp & 1;
    const int wn   = warp >> 1;
    const int bx = blockIdx.x;
    const int by = blockIdx.y;

    const char* aSrc = (const char*)(g_adjb + (size_t)(by * 128) * N_);
    const char* bSrc = (const char*)(g_gT   + (size_t)(bx * 128) * N_);

    float acc[4][4][4];
#pragma unroll
    for (int i = 0; i < 4; i++)
#pragma unroll
        for (int j = 0; j < 4; j++)
#pragma unroll
            for (int v = 0; v < 4; v++) acc[i][j][v] = 0.0f;

    const int ldRow = tid >> 3;
    const int ldCol = tid & 7;

    auto issue = [&](int kt, int s) {
        const uint32_t aB = sb + s * AJ_STAGE_B;
        const uint32_t bB = aB + AJ_TILE;
#pragma unroll
        for (int i = 0; i < 4; i++) {
            const int row = ldRow + 32 * i;
            const uint32_t so = swz((uint32_t)(row * 128 + ldCol * 16));
            const size_t gsrc = (size_t)row * (N_ * 2) + kt * 128 + ldCol * 16;
            cp16(aB + so, aSrc + gsrc);
            cp16(bB + so, bSrc + gsrc);
        }
    };

    auto compute = [&](int s) {
        const uint32_t aB = sb + s * AJ_STAGE_B;
        const uint32_t bB = aB + AJ_TILE;
#pragma unroll
        for (int ks = 0; ks < 4; ks++) {
            const int k0b = ks * 32;
            uint32_t af[4][4], bf[2][4];
#pragma unroll
            for (int mt = 0; mt < 4; mt++) {
                const int row = wm * 64 + mt * 16 + (lane & 15);
                ldsm4(af[mt], aB + swz((uint32_t)(row * 128 + k0b + ((lane >> 4) << 4))));
            }
#pragma unroll
            for (int p = 0; p < 2; p++) {
                const int row = wn * 32 + p * 16 + (lane & 7) + ((lane >> 4) << 3);
                ldsm4(bf[p], bB + swz((uint32_t)(row * 128 + k0b + (((lane >> 3) & 1) << 4))));
            }
#pragma unroll
            for (int mt = 0; mt < 4; mt++)
#pragma unroll
                for (int nt = 0; nt < 4; nt++)
                    mma16816(acc[mt][nt], af[mt], &bf[nt >> 1][(nt & 1) * 2]);
        }
    };

    issue(0, 0);
    asm volatile("cp.async.commit_group;" ::: "memory");
    issue(1, 1);
    asm volatile("cp.async.commit_group;" ::: "memory");
    for (int kt = 0; kt < AJ_NK; kt++) {
        asm volatile("cp.async.wait_group 1;" ::: "memory");
        __syncthreads();
        compute(kt % 3);
        const int f = kt + 2;
        if (f < AJ_NK) issue(f, f % 3);
        asm volatile("cp.async.commit_group;" ::: "memory");
    }

    // fused epilogue: half-update into h (fp32), hb (bf16), out
#pragma unroll
    for (int mt = 0; mt < 4; mt++) {
        const int node0 = by * 128 + wm * 64 + mt * 16 + (lane >> 2);
#pragma unroll
        for (int nt = 0; nt < 4; nt++) {
            const int col = bx * 128 + wn * 32 + nt * 8 + 2 * (lane & 3);
            const int b  = col >> 6;
            const int dh = col & 63;
#pragma unroll
            for (int r = 0; r < 2; r++) {
                const int node = node0 + r * 8;
                const float t0 = acc[mt][nt][2 * r + 0];
                const float t1 = acc[mt][nt][2 * r + 1];
                const size_t bn = (size_t)b * N_ + node;
                const size_t hi = bn * D_ + HID * HALF_ + dh;
                float2 hv = *reinterpret_cast<const float2*>(g_h + hi);
                if (HID == 0) {
                    hv.x += DT_ * tanh_fast(t0);
                    hv.y += DT_ * tanh_fast(t1);
                } else {
                    float2 ev = *reinterpret_cast<const float2*>(eps + bn * HALF_ + dh);
                    ev.x = fminf(fmaxf(ev.x, 0.0f), 0.1f);
                    ev.y = fminf(fmaxf(ev.y, 0.0f), 0.1f);
                    hv.x = ev.x * (hv.x + DT_ * tanh_fast(t0));
                    hv.y = ev.y * (hv.y + DT_ * tanh_fast(t1));
                }
                *reinterpret_cast<float2*>(g_h + hi) = hv;
                *reinterpret_cast<__nv_bfloat162*>(g_hb + hi) =
                    __floats2bfloat162_rn(hv.x, hv.y);
                *reinterpret_cast<float2*>(out + hi) = hv;
            }
        }
    }
}

// ===========================================================================
extern "C" void kernel_launch(void* const* d_in, const int* /*in_sizes*/,
                              int /*n_in*/, void* d_out, int /*out_size*/)
{
    const float* x   = (const float*)d_in[0];
    const float* hz  = (const float*)d_in[1];
    const float* adj = (const float*)d_in[2];
    const float* W1  = (const float*)d_in[3];
    const float* W2  = (const float*)d_in[4];
    const float* Wa  = (const float*)d_in[5];
    const float* ba  = (const float*)d_in[6];
    const float* Wb  = (const float*)d_in[7];
    const float* bb  = (const float*)d_in[8];
    const float* eps = (const float*)d_in[9];
    float* out = (float*)d_out;

    __nv_bfloat16 *xh_hi, *xh_lo, *WaT_hi, *WaT_lo;
    __nv_bfloat16 *a_hi, *a_lo, *WbT_hi, *WbT_lo;
    __nv_bfloat16 *W1Tb, *W2Tb, *gT_p;
    cudaGetSymbolAddress((void**)&xh_hi, g_xh_hi);
    cudaGetSymbolAddress((void**)&xh_lo, g_xh_lo);
    cudaGetSymbolAddress((void**)&WaT_hi, g_WaT_hi);
    cudaGetSymbolAddress((void**)&WaT_lo, g_WaT_lo);
    cudaGetSymbolAddress((void**)&a_hi, g_a_hi);
    cudaGetSymbolAddress((void**)&a_lo, g_a_lo);
    cudaGetSymbolAddress((void**)&WbT_hi, g_WbT_hi);
    cudaGetSymbolAddress((void**)&WbT_lo, g_WbT_lo);
    cudaGetSymbolAddress((void**)&W1Tb, g_W1Tb);
    cudaGetSymbolAddress((void**)&W2Tb, g_W2Tb);
    cudaGetSymbolAddress((void**)&gT_p, g_gT);

    cudaFuncSetAttribute(mlp_mma_k<1>,
                         cudaFuncAttributeMaxDynamicSharedMemorySize, MLP_SMEM);
    cudaFuncSetAttribute(mlp_mma_k<2>,
                         cudaFuncAttributeMaxDynamicSharedMemorySize, MLP_SMEM);
    cudaFuncSetAttribute(gproj_k,
                         cudaFuncAttributeMaxDynamicSharedMemorySize, GP_SMEM);
    cudaFuncSetAttribute(adj_mma_k<0>,
                         cudaFuncAttributeMaxDynamicSharedMemorySize, ADJ_SMEM);
    cudaFuncSetAttribute(adj_mma_k<1>,
                         cudaFuncAttributeMaxDynamicSharedMemorySize, ADJ_SMEM);

    const dim3 blk(256);
    const dim3 adjGrid(N_ / 128, N_ / 128);

    cvt_adj_k<<<(N_ * N_) / 1024, blk>>>(adj);
    cvt_xh_k<<<16384, blk>>>(x, hz);
    cvt_w_k<<<448, blk>>>(Wa, Wb, W1, W2);

    mlp_mma_k<1><<<dim3(2, M_ROWS / 128), blk, MLP_SMEM>>>(
        xh_hi, xh_lo, WaT_hi, WaT_lo, ba);
    mlp_mma_k<2><<<dim3(1, M_ROWS / 128), blk, MLP_SMEM>>>(
        a_hi, a_lo, WbT_hi, WbT_lo, bb);

    for (int it = 0; it < 2; ++it) {
        gproj_k<<<dim3(1, M_ROWS / 128), blk, GP_SMEM>>>(W1Tb, gT_p);
        adj_mma_k<0><<<adjGrid, blk, ADJ_SMEM>>>(out, eps);
        gproj_k<<<dim3(1, M_ROWS / 128), blk, GP_SMEM>>>(W2Tb, gT_p);
        adj_mma_k<1><<<adjGrid, blk, ADJ_SMEM>>>(out, eps);
    }
}

// round 10
// speedup vs baseline: 2.0157x; 1.0269x over previous
#include <cuda_runtime.h>
#include <cuda_bf16.h>
#include <math.h>
#include <stdint.h>

// Problem constants
static constexpr int B_    = 32;
static constexpr int N_    = 2048;
static constexpr int D_    = 128;
static constexpr int HALF_ = 64;
static constexpr float DT_ = 0.01f;
static constexpr int M_ROWS = B_ * N_;   // 65536

// Scratch (static device globals)
__device__ float         g_h  [M_ROWS * D_];      // h fp32 [B][N][D]
__device__ __nv_bfloat16 g_hb [M_ROWS * D_];      // bf16 mirror of h
__device__ __nv_bfloat16 g_adjb[N_ * N_];         // adj bf16
__device__ __nv_bfloat16 g_gT [N_ * N_];          // gT [b*64+dh][node]
__device__ __nv_bfloat16 g_xh_hi[M_ROWS * 256];   // concat(x,hz) hi
__device__ __nv_bfloat16 g_xh_lo[M_ROWS * 256];   // concat(x,hz) lo
__device__ __nv_bfloat16 g_a_hi [M_ROWS * 256];   // relu hidden hi
__device__ __nv_bfloat16 g_a_lo [M_ROWS * 256];   // relu hidden lo
__device__ __nv_bfloat16 g_WaT_hi[256 * 256], g_WaT_lo[256 * 256];
__device__ __nv_bfloat16 g_WbT_hi[128 * 256], g_WbT_lo[128 * 256];
__device__ __nv_bfloat16 g_W1Tb[64 * 128], g_W2Tb[64 * 128];

__device__ __forceinline__ float4 ld4(const float* p) {
    return *reinterpret_cast<const float4*>(p);
}
__device__ __forceinline__ uint32_t s2u(const void* p) {
    uint32_t r;
    asm("{ .reg .u64 t; cvta.to.shared.u64 t, %1; cvt.u32.u64 %0, t; }"
        : "=r"(r) : "l"(p));
    return r;
}
__device__ __forceinline__ void cp16(uint32_t d, const void* s) {
    asm volatile("cp.async.cg.shared.global [%0], [%1], 16;" :: "r"(d), "l"(s) : "memory");
}
__device__ __forceinline__ uint32_t swz(uint32_t o)   { return o ^ ((o >> 3) & 0x70); }
__device__ __forceinline__ uint32_t swz64(uint32_t o) { return o ^ ((o >> 3) & 0x30); }
__device__ __forceinline__ float tanh_fast(float x) {
    float y;
    asm("tanh.approx.f32 %0, %1;" : "=f"(y) : "f"(x));
    return y;
}
__device__ __forceinline__ void ldsm4(uint32_t (&r)[4], uint32_t addr) {
    asm volatile("ldmatrix.sync.aligned.m8n8.x4.shared.b16 {%0,%1,%2,%3}, [%4];"
                 : "=r"(r[0]), "=r"(r[1]), "=r"(r[2]), "=r"(r[3]) : "r"(addr));
}
__device__ __forceinline__ void mma16816(float (&c)[4], const uint32_t (&a)[4],
                                         const uint32_t* b) {
    asm volatile(
        "mma.sync.aligned.m16n8k16.row.col.f32.bf16.bf16.f32 "
        "{%0,%1,%2,%3}, {%4,%5,%6,%7}, {%8,%9}, {%0,%1,%2,%3};"
        : "+f"(c[0]), "+f"(c[1]), "+f"(c[2]), "+f"(c[3])
        : "r"(a[0]), "r"(a[1]), "r"(a[2]), "r"(a[3]), "r"(b[0]), "r"(b[1]));
}
__device__ __forceinline__ void split2(float v, __nv_bfloat16& hi, __nv_bfloat16& lo) {
    hi = __float2bfloat16(v);
    lo = __float2bfloat16(v - __bfloat162float(hi));
}
__device__ __forceinline__ __nv_bfloat162 pack2(__nv_bfloat16 a, __nv_bfloat16 b) {
    __nv_bfloat162 r; r.x = a; r.y = b; return r;
}

// ===========================================================================
// Conversion kernels
// ===========================================================================
__global__ __launch_bounds__(256) void cvt_adj_k(const float* __restrict__ a)
{
    const int i = blockIdx.x * 256 + threadIdx.x;
    float4 v = ld4(a + (size_t)i * 4);
    *reinterpret_cast<__nv_bfloat162*>(g_adjb + (size_t)i * 4)     =
        __floats2bfloat162_rn(v.x, v.y);
    *reinterpret_cast<__nv_bfloat162*>(g_adjb + (size_t)i * 4 + 2) =
        __floats2bfloat162_rn(v.z, v.w);
}

__global__ __launch_bounds__(256) void cvt_xh_k(const float* __restrict__ x,
                                                const float* __restrict__ hz)
{
    const int i = blockIdx.x * 256 + threadIdx.x;
    const bool isHz = i >= 2097152;
    const int j = isHz ? i - 2097152 : i;
    const int row = j >> 5;
    const int c4  = (j & 31) * 4;
    float4 v = ld4((isHz ? hz : x) + (size_t)row * 128 + c4);
    __nv_bfloat16 h0, l0, h1, l1, h2, l2, h3, l3;
    split2(v.x, h0, l0); split2(v.y, h1, l1);
    split2(v.z, h2, l2); split2(v.w, h3, l3);
    const size_t o = (size_t)row * 256 + (isHz ? 128 : 0) + c4;
    *reinterpret_cast<__nv_bfloat162*>(g_xh_hi + o)     = pack2(h0, h1);
    *reinterpret_cast<__nv_bfloat162*>(g_xh_hi + o + 2) = pack2(h2, h3);
    *reinterpret_cast<__nv_bfloat162*>(g_xh_lo + o)     = pack2(l0, l1);
    *reinterpret_cast<__nv_bfloat162*>(g_xh_lo + o + 2) = pack2(l2, l3);
}

__global__ __launch_bounds__(256) void cvt_w_k(const float* __restrict__ Wa,
                                               const float* __restrict__ Wb,
                                               const float* __restrict__ W1,
                                               const float* __restrict__ W2)
{
    const int i = blockIdx.x * 256 + threadIdx.x;
    if (i < 65536) {
        const int n = i >> 8, k = i & 255;
        __nv_bfloat16 hi, lo;
        split2(Wa[k * 256 + n], hi, lo);
        g_WaT_hi[i] = hi; g_WaT_lo[i] = lo;
    } else if (i < 65536 + 32768) {
        const int j = i - 65536;
        const int n = j >> 8, k = j & 255;
        __nv_bfloat16 hi, lo;
        split2(Wb[k * 128 + n], hi, lo);
        g_WbT_hi[j] = hi; g_WbT_lo[j] = lo;
    } else if (i < 65536 + 32768 + 8192) {
        const int j = i - 65536 - 32768;
        const int dh = j >> 7, k = j & 127;
        g_W1Tb[j] = __float2bfloat16(W1[k * 128 + dh]);
    } else if (i < 65536 + 32768 + 16384) {
        const int j = i - 65536 - 32768 - 8192;
        const int dh = j >> 7, k = j & 127;
        g_W2Tb[j] = __float2bfloat16(W2[k * 128 + 64 + dh]);
    }
}

// ===========================================================================
// MLP GEMM (bf16x3 split): C = act(A @ W^T + bias)
// CTA 128x128, K=256 in 8 chunks of 32 (64B rows, SW64 swizzle),
// 3-stage cp.async (96KB), 2 CTAs/SM.
// Register-lean compute: B frags loaded per 16-col half and consumed
// immediately (live B regs 8 instead of 32) -> no spills at the 128-reg cap.
// ===========================================================================
static constexpr int MLP_STG_B = 32768;
static constexpr int MLP_SMEM  = 3 * MLP_STG_B;   // 98304
static constexpr int MLP_NK    = 8;               // 256 / 32

template <int MODE>
__global__ __launch_bounds__(256, 2) void mlp_mma_k(
    const __nv_bfloat16* __restrict__ Ahi, const __nv_bfloat16* __restrict__ Alo,
    const __nv_bfloat16* __restrict__ Bhi, const __nv_bfloat16* __restrict__ Blo,
    const float* __restrict__ bias)
{
    extern __shared__ char smem[];
    const uint32_t sb = s2u(smem);
    const int tid  = threadIdx.x;
    const int lane = tid & 31;
    const int warp = tid >> 5;
    const int wm   = warp & 1;       // 2 warps M (64 each)
    const int wn   = warp >> 1;      // 4 warps N (32 each)
    const int bx = blockIdx.x;
    const int by = blockIdx.y;

    float acc[4][4][4];
#pragma unroll
    for (int i = 0; i < 4; i++)
#pragma unroll
        for (int j = 0; j < 4; j++)
#pragma unroll
            for (int v = 0; v < 4; v++) acc[i][j][v] = 0.0f;

    const int ldRow  = tid >> 1;         // 0..127
    const int ldHalf = tid & 1;          // 2 x 16B chunks each

    auto issue = [&](int c, int s) {
        const uint32_t st = sb + s * MLP_STG_B;
        const size_t aOff = (size_t)(by * 128 + ldRow) * 256 + c * 32;
        const size_t bOff = (size_t)(bx * 128 + ldRow) * 256 + c * 32;
#pragma unroll
        for (int j = 0; j < 2; j++) {
            const int chunk = ldHalf * 2 + j;
            const uint32_t so = swz64((uint32_t)(ldRow * 64 + chunk * 16));
            const int e = chunk * 8;
            cp16(st + so,          Ahi + aOff + e);
            cp16(st + 8192 + so,   Alo + aOff + e);
            cp16(st + 16384 + so,  Bhi + bOff + e);
            cp16(st + 24576 + so,  Blo + bOff + e);
        }
    };

    auto compute = [&](int s) {
        const uint32_t st = sb + s * MLP_STG_B;
#pragma unroll
        for (int ks = 0; ks < 2; ks++) {
            const int k0b = ks * 32;
            uint32_t ah[4][4], al[4][4];
#pragma unroll
            for (int mt = 0; mt < 4; mt++) {
                const int row = wm * 64 + mt * 16 + (lane & 15);
                const uint32_t o = swz64((uint32_t)(row * 64 + k0b + ((lane >> 4) << 4)));
                ldsm4(ah[mt], st + o);
                ldsm4(al[mt], st + 8192 + o);
            }
            // process B in 16-col halves to keep frag registers low
#pragma unroll
            for (int p = 0; p < 2; p++) {
                uint32_t bh[4], bl[4];
                const int row = wn * 32 + p * 16 + (lane & 7) + ((lane >> 4) << 3);
                const uint32_t o = swz64((uint32_t)(row * 64 + k0b + (((lane >> 3) & 1) << 4)));
                ldsm4(bh, st + 16384 + o);
                ldsm4(bl, st + 24576 + o);
#pragma unroll
                for (int mt = 0; mt < 4; mt++)
#pragma unroll
                    for (int sub = 0; sub < 2; sub++) {
                        const int nt = p * 2 + sub;
                        mma16816(acc[mt][nt], ah[mt], &bh[sub * 2]);
                        mma16816(acc[mt][nt], ah[mt], &bl[sub * 2]);
                        mma16816(acc[mt][nt], al[mt], &bh[sub * 2]);
                    }
            }
        }
    };

    issue(0, 0);
    asm volatile("cp.async.commit_group;" ::: "memory");
    issue(1, 1);
    asm volatile("cp.async.commit_group;" ::: "memory");
    for (int kt = 0; kt < MLP_NK; kt++) {
        asm volatile("cp.async.wait_group 1;" ::: "memory");
        __syncthreads();
        compute(kt % 3);
        if (kt + 2 < MLP_NK) issue(kt + 2, (kt + 2) % 3);
        asm volatile("cp.async.commit_group;" ::: "memory");
    }

#pragma unroll
    for (int mt = 0; mt < 4; mt++) {
        const int row0 = by * 128 + wm * 64 + mt * 16 + (lane >> 2);
#pragma unroll
        for (int nt = 0; nt < 4; nt++) {
            const int col = bx * 128 + wn * 32 + nt * 8 + 2 * (lane & 3);
            const float b0 = bias[col], b1 = bias[col + 1];
#pragma unroll
            for (int r = 0; r < 2; r++) {
                const int row = row0 + r * 8;
                float v0 = acc[mt][nt][2 * r + 0] + b0;
                float v1 = acc[mt][nt][2 * r + 1] + b1;
                if (MODE == 1) {
                    v0 = fmaxf(v0, 0.0f);
                    v1 = fmaxf(v1, 0.0f);
                    __nv_bfloat16 h0, l0, h1, l1;
                    split2(v0, h0, l0); split2(v1, h1, l1);
                    const size_t o = (size_t)row * 256 + col;
                    *reinterpret_cast<__nv_bfloat162*>(g_a_hi + o) = pack2(h0, h1);
                    *reinterpret_cast<__nv_bfloat162*>(g_a_lo + o) = pack2(l0, l1);
                } else {
                    v0 = tanhf(v0);
                    v1 = tanhf(v1);
                    const size_t o = (size_t)row * 128 + col;
                    *reinterpret_cast<float2*>(g_h + o) = make_float2(v0, v1);
                    *reinterpret_cast<__nv_bfloat162*>(g_hb + o) =
                        __floats2bfloat162_rn(v0, v1);
                }
            }
        }
    }
}

// ===========================================================================
// gproj (bf16 mma): g = hb @ WTb^T, bf16 output transposed into gT.
// CTA 128 rows x 64 cols, K=128. 2 CTAs/SM.
// ===========================================================================
static constexpr int GP_SMEM = 49152 + 128 * 68 * 2;

__global__ __launch_bounds__(256, 2) void gproj_k(
    const __nv_bfloat16* __restrict__ WTb, __nv_bfloat16* __restrict__ gT)
{
    extern __shared__ char smem[];
    const uint32_t sb = s2u(smem);
    unsigned short* Ts = reinterpret_cast<unsigned short*>(smem + 49152);
    const int tid  = threadIdx.x;
    const int lane = tid & 31;
    const int warp = tid >> 5;
    const int wm   = warp & 3;
    const int wn   = warp >> 2;
    const int by = blockIdx.y;

    {
        const int r = tid >> 1, half = tid & 1;
        const size_t rowOff = (size_t)(by * 128 + r) * 128;
#pragma unroll
        for (int c = 0; c < 2; c++)
#pragma unroll
            for (int j = 0; j < 4; j++) {
                const uint32_t so = swz((uint32_t)(r * 128 + (half * 4 + j) * 16));
                cp16(sb + c * 16384 + so, g_hb + rowOff + c * 64 + (half * 4 + j) * 8);
            }
    }
    {
        const int r = tid >> 2, q = tid & 3;
#pragma unroll
        for (int c = 0; c < 2; c++)
#pragma unroll
            for (int j = 0; j < 2; j++) {
                const uint32_t so = swz((uint32_t)(r * 128 + (q * 2 + j) * 16));
                cp16(sb + 32768 + c * 8192 + so,
                     WTb + (size_t)r * 128 + c * 64 + (q * 2 + j) * 8);
            }
    }
    asm volatile("cp.async.commit_group;" ::: "memory");
    asm volatile("cp.async.wait_group 0;" ::: "memory");
    __syncthreads();

    float acc[2][4][4];
#pragma unroll
    for (int i = 0; i < 2; i++)
#pragma unroll
        for (int j = 0; j < 4; j++)
#pragma unroll
            for (int v = 0; v < 4; v++) acc[i][j][v] = 0.0f;

#pragma unroll
    for (int c = 0; c < 2; c++) {
        const uint32_t aB = sb + c * 16384;
        const uint32_t bB = sb + 32768 + c * 8192;
#pragma unroll
        for (int ks = 0; ks < 4; ks++) {
            const int k0b = ks * 32;
            uint32_t af[2][4], bf[2][4];
#pragma unroll
            for (int mt = 0; mt < 2; mt++) {
                const int row = wm * 32 + mt * 16 + (lane & 15);
                ldsm4(af[mt], aB + swz((uint32_t)(row * 128 + k0b + ((lane >> 4) << 4))));
            }
#pragma unroll
            for (int p = 0; p < 2; p++) {
                const int row = wn * 32 + p * 16 + (lane & 7) + ((lane >> 4) << 3);
                ldsm4(bf[p], bB + swz((uint32_t)(row * 128 + k0b + (((lane >> 3) & 1) << 4))));
            }
#pragma unroll
            for (int mt = 0; mt < 2; mt++)
#pragma unroll
                for (int nt = 0; nt < 4; nt++)
                    mma16816(acc[mt][nt], af[mt], &bf[nt >> 1][(nt & 1) * 2]);
        }
    }
    __syncthreads();

#pragma unroll
    for (int mt = 0; mt < 2; mt++) {
        const int row0 = wm * 32 + mt * 16 + (lane >> 2);
#pragma unroll
        for (int nt = 0; nt < 4; nt++) {
            const int col = wn * 32 + nt * 8 + 2 * (lane & 3);
#pragma unroll
            for (int r = 0; r < 2; r++) {
                const int row = row0 + r * 8;
                __nv_bfloat16 b0 = __float2bfloat16(acc[mt][nt][2 * r + 0]);
                __nv_bfloat16 b1 = __float2bfloat16(acc[mt][nt][2 * r + 1]);
                Ts[row * 68 + col]     = *reinterpret_cast<unsigned short*>(&b0);
                Ts[row * 68 + col + 1] = *reinterpret_cast<unsigned short*>(&b1);
            }
        }
    }
    __syncthreads();

    const int colp = tid & 63;
    const int seg  = tid >> 6;
    const int b    = by >> 4;
    const int n0   = (by & 15) * 128;
    __nv_bfloat16* dst = gT + (size_t)(b * 64 + colp) * N_ + n0 + seg * 32;
#pragma unroll
    for (int q = 0; q < 4; q++) {
        const int r0 = seg * 32 + q * 8;
        uint32_t w[4];
#pragma unroll
        for (int p = 0; p < 4; p++) {
            uint32_t lo = Ts[(r0 + 2 * p) * 68 + colp];
            uint32_t hi = Ts[(r0 + 2 * p + 1) * 68 + colp];
            w[p] = lo | (hi << 16);
        }
        *reinterpret_cast<uint4*>(dst + q * 8) = make_uint4(w[0], w[1], w[2], w[3]);
    }
}

// ===========================================================================
// adj GEMM (bf16 mma) + fused half-update epilogue.
// CTA 128x128, BK=64, 3-stage cp.async (96 KB), 2 CTAs/SM.
// Templates: WOUT = write d_out (only needed on last iteration);
//            WH   = write h/hb (not needed on the very last launch).
// ===========================================================================
static constexpr int AJ_STAGES  = 3;
static constexpr int AJ_NK      = N_ / 64;         // 32
static constexpr int AJ_TILE    = 16384;
static constexpr int AJ_STAGE_B = 2 * AJ_TILE;
static constexpr int ADJ_SMEM   = AJ_STAGES * AJ_STAGE_B;   // 96 KB

template <int HID, bool WOUT, bool WH>
__global__ __launch_bounds__(256, 2) void adj_mma_k(
    float* __restrict__ out, const float* __restrict__ eps)
{
    extern __shared__ char smem[];
    const uint32_t sb = s2u(smem);
    const int tid  = threadIdx.x;
    const int lane = tid & 31;
    const int warp = tid >> 5;
    const int wm   = warp & 1;
    const int wn   = warp >> 1;
    const int bx = blockIdx.x;
    const int by = blockIdx.y;

    const char* aSrc = (const char*)(g_adjb + (size_t)(by * 128) * N_);
    const char* bSrc = (const char*)(g_gT   + (size_t)(bx * 128) * N_);

    float acc[4][4][4];
#pragma unroll
    for (int i = 0; i < 4; i++)
#pragma unroll
        for (int j = 0; j < 4; j++)
#pragma unroll
            for (int v = 0; v < 4; v++) acc[i][j][v] = 0.0f;

    const int ldRow = tid >> 3;
    const int ldCol = tid & 7;

    auto issue = [&](int kt, int s) {
        const uint32_t aB = sb + s * AJ_STAGE_B;
        const uint32_t bB = aB + AJ_TILE;
#pragma unroll
        for (int i = 0; i < 4; i++) {
            const int row = ldRow + 32 * i;
            const uint32_t so = swz((uint32_t)(row * 128 + ldCol * 16));
            const size_t gsrc = (size_t)row * (N_ * 2) + kt * 128 + ldCol * 16;
            cp16(aB + so, aSrc + gsrc);
            cp16(bB + so, bSrc + gsrc);
        }
    };

    auto compute = [&](int s) {
        const uint32_t aB = sb + s * AJ_STAGE_B;
        const uint32_t bB = aB + AJ_TILE;
#pragma unroll
        for (int ks = 0; ks < 4; ks++) {
            const int k0b = ks * 32;
            uint32_t af[4][4], bf[2][4];
#pragma unroll
            for (int mt = 0; mt < 4; mt++) {
                const int row = wm * 64 + mt * 16 + (lane & 15);
                ldsm4(af[mt], aB + swz((uint32_t)(row * 128 + k0b + ((lane >> 4) << 4))));
            }
#pragma unroll
            for (int p = 0; p < 2; p++) {
                const int row = wn * 32 + p * 16 + (lane & 7) + ((lane >> 4) << 3);
                ldsm4(bf[p], bB + swz((uint32_t)(row * 128 + k0b + (((lane >> 3) & 1) << 4))));
            }
#pragma unroll
            for (int mt = 0; mt < 4; mt++)
#pragma unroll
                for (int nt = 0; nt < 4; nt++)
                    mma16816(acc[mt][nt], af[mt], &bf[nt >> 1][(nt & 1) * 2]);
        }
    };

    issue(0, 0);
    asm volatile("cp.async.commit_group;" ::: "memory");
    issue(1, 1);
    asm volatile("cp.async.commit_group;" ::: "memory");
    for (int kt = 0; kt < AJ_NK; kt++) {
        asm volatile("cp.async.wait_group 1;" ::: "memory");
        __syncthreads();
        compute(kt % 3);
        const int f = kt + 2;
        if (f < AJ_NK) issue(f, f % 3);
        asm volatile("cp.async.commit_group;" ::: "memory");
    }

    // fused epilogue
#pragma unroll
    for (int mt = 0; mt < 4; mt++) {
        const int node0 = by * 128 + wm * 64 + mt * 16 + (lane >> 2);
#pragma unroll
        for (int nt = 0; nt < 4; nt++) {
            const int col = bx * 128 + wn * 32 + nt * 8 + 2 * (lane & 3);
            const int b  = col >> 6;
            const int dh = col & 63;
#pragma unroll
            for (int r = 0; r < 2; r++) {
                const int node = node0 + r * 8;
                const float t0 = acc[mt][nt][2 * r + 0];
                const float t1 = acc[mt][nt][2 * r + 1];
                const size_t bn = (size_t)b * N_ + node;
                const size_t hi = bn * D_ + HID * HALF_ + dh;
                float2 hv = *reinterpret_cast<const float2*>(g_h + hi);
                if (HID == 0) {
                    hv.x += DT_ * tanh_fast(t0);
                    hv.y += DT_ * tanh_fast(t1);
                } else {
                    float2 ev = *reinterpret_cast<const float2*>(eps + bn * HALF_ + dh);
                    ev.x = fminf(fmaxf(ev.x, 0.0f), 0.1f);
                    ev.y = fminf(fmaxf(ev.y, 0.0f), 0.1f);
                    hv.x = ev.x * (hv.x + DT_ * tanh_fast(t0));
                    hv.y = ev.y * (hv.y + DT_ * tanh_fast(t1));
                }
                if (WH) {
                    *reinterpret_cast<float2*>(g_h + hi) = hv;
                    *reinterpret_cast<__nv_bfloat162*>(g_hb + hi) =
                        __floats2bfloat162_rn(hv.x, hv.y);
                }
                if (WOUT)
                    *reinterpret_cast<float2*>(out + hi) = hv;
            }
        }
    }
}

// ===========================================================================
extern "C" void kernel_launch(void* const* d_in, const int* /*in_sizes*/,
                              int /*n_in*/, void* d_out, int /*out_size*/)
{
    const float* x   = (const float*)d_in[0];
    const float* hz  = (const float*)d_in[1];
    const float* adj = (const float*)d_in[2];
    const float* W1  = (const float*)d_in[3];
    const float* W2  = (const float*)d_in[4];
    const float* Wa  = (const float*)d_in[5];
    const float* ba  = (const float*)d_in[6];
    const float* Wb  = (const float*)d_in[7];
    const float* bb  = (const float*)d_in[8];
    const float* eps = (const float*)d_in[9];
    float* out = (float*)d_out;

    __nv_bfloat16 *xh_hi, *xh_lo, *WaT_hi, *WaT_lo;
    __nv_bfloat16 *a_hi, *a_lo, *WbT_hi, *WbT_lo;
    __nv_bfloat16 *W1Tb, *W2Tb, *gT_p;
    cudaGetSymbolAddress((void**)&xh_hi, g_xh_hi);
    cudaGetSymbolAddress((void**)&xh_lo, g_xh_lo);
    cudaGetSymbolAddress((void**)&WaT_hi, g_WaT_hi);
    cudaGetSymbolAddress((void**)&WaT_lo, g_WaT_lo);
    cudaGetSymbolAddress((void**)&a_hi, g_a_hi);
    cudaGetSymbolAddress((void**)&a_lo, g_a_lo);
    cudaGetSymbolAddress((void**)&WbT_hi, g_WbT_hi);
    cudaGetSymbolAddress((void**)&WbT_lo, g_WbT_lo);
    cudaGetSymbolAddress((void**)&W1Tb, g_W1Tb);
    cudaGetSymbolAddress((void**)&W2Tb, g_W2Tb);
    cudaGetSymbolAddress((void**)&gT_p, g_gT);

    cudaFuncSetAttribute(mlp_mma_k<1>,
                         cudaFuncAttributeMaxDynamicSharedMemorySize, MLP_SMEM);
    cudaFuncSetAttribute(mlp_mma_k<2>,
                         cudaFuncAttributeMaxDynamicSharedMemorySize, MLP_SMEM);
    cudaFuncSetAttribute(gproj_k,
                         cudaFuncAttributeMaxDynamicSharedMemorySize, GP_SMEM);
    cudaFuncSetAttribute((const void*)adj_mma_k<0, false, true>,
                         cudaFuncAttributeMaxDynamicSharedMemorySize, ADJ_SMEM);
    cudaFuncSetAttribute((const void*)adj_mma_k<1, false, true>,
                         cudaFuncAttributeMaxDynamicSharedMemorySize, ADJ_SMEM);
    cudaFuncSetAttribute((const void*)adj_mma_k<0, true, true>,
                         cudaFuncAttributeMaxDynamicSharedMemorySize, ADJ_SMEM);
    cudaFuncSetAttribute((const void*)adj_mma_k<1, true, false>,
                         cudaFuncAttributeMaxDynamicSharedMemorySize, ADJ_SMEM);

    const dim3 blk(256);
    const dim3 adjGrid(N_ / 128, N_ / 128);

    cvt_adj_k<<<(N_ * N_) / 1024, blk>>>(adj);
    cvt_xh_k<<<16384, blk>>>(x, hz);
    cvt_w_k<<<448, blk>>>(Wa, Wb, W1, W2);

    mlp_mma_k<1><<<dim3(2, M_ROWS / 128), blk, MLP_SMEM>>>(
        xh_hi, xh_lo, WaT_hi, WaT_lo, ba);
    mlp_mma_k<2><<<dim3(1, M_ROWS / 128), blk, MLP_SMEM>>>(
        a_hi, a_lo, WbT_hi, WbT_lo, bb);

    // iteration 0: out writes skipped (overwritten by iteration 1)
    gproj_k<<<dim3(1, M_ROWS / 128), blk, GP_SMEM>>>(W1Tb, gT_p);
    adj_mma_k<0, false, true><<<adjGrid, blk, ADJ_SMEM>>>(out, eps);
    gproj_k<<<dim3(1, M_ROWS / 128), blk, GP_SMEM>>>(W2Tb, gT_p);
    adj_mma_k<1, false, true><<<adjGrid, blk, ADJ_SMEM>>>(out, eps);

    // iteration 1: write out; final launch skips dead h/hb stores
    gproj_k<<<dim3(1, M_ROWS / 128), blk, GP_SMEM>>>(W1Tb, gT_p);
    adj_mma_k<0, true, true><<<adjGrid, blk, ADJ_SMEM>>>(out, eps);
    gproj_k<<<dim3(1, M_ROWS / 128), blk, GP_SMEM>>>(W2Tb, gT_p);
    adj_mma_k<1, true, false><<<adjGrid, blk, ADJ_SMEM>>>(out, eps);
}

// round 11
// speedup vs baseline: 2.2535x; 1.1180x over previous
#include <cuda_runtime.h>
#include <cuda_bf16.h>
#include <cuda_fp16.h>
#include <math.h>
#include <stdint.h>

// Problem constants
static constexpr int B_    = 32;
static constexpr int N_    = 2048;
static constexpr int D_    = 128;
static constexpr int HALF_ = 64;
static constexpr float DT_ = 0.01f;
static constexpr int M_ROWS = B_ * N_;   // 65536

// Scratch (static device globals)
__device__ float         g_h  [M_ROWS * D_];      // h fp32 [B][N][D]
__device__ __nv_bfloat16 g_hb [M_ROWS * D_];      // bf16 mirror of h
__device__ __nv_bfloat16 g_adjb[N_ * N_];         // adj bf16
__device__ __nv_bfloat16 g_gT [N_ * N_];          // gT [b*64+dh][node]
__device__ __half        g_xh [M_ROWS * 256];     // concat(x,hz) fp16
__device__ __half        g_af [M_ROWS * 256];     // relu hidden fp16
__device__ __half        g_WaT_h[256 * 256], g_WaT_l[256 * 256];
__device__ __half        g_WbT_h[128 * 256], g_WbT_l[128 * 256];
__device__ __nv_bfloat16 g_W1Tb[64 * 128], g_W2Tb[64 * 128];

__device__ __forceinline__ float4 ld4(const float* p) {
    return *reinterpret_cast<const float4*>(p);
}
__device__ __forceinline__ uint32_t s2u(const void* p) {
    uint32_t r;
    asm("{ .reg .u64 t; cvta.to.shared.u64 t, %1; cvt.u32.u64 %0, t; }"
        : "=r"(r) : "l"(p));
    return r;
}
__device__ __forceinline__ void cp16(uint32_t d, const void* s) {
    asm volatile("cp.async.cg.shared.global [%0], [%1], 16;" :: "r"(d), "l"(s) : "memory");
}
__device__ __forceinline__ uint32_t swz(uint32_t o)   { return o ^ ((o >> 3) & 0x70); }
__device__ __forceinline__ uint32_t swz64(uint32_t o) { return o ^ ((o >> 3) & 0x30); }
__device__ __forceinline__ float tanh_fast(float x) {
    float y;
    asm("tanh.approx.f32 %0, %1;" : "=f"(y) : "f"(x));
    return y;
}
__device__ __forceinline__ void ldsm4(uint32_t (&r)[4], uint32_t addr) {
    asm volatile("ldmatrix.sync.aligned.m8n8.x4.shared.b16 {%0,%1,%2,%3}, [%4];"
                 : "=r"(r[0]), "=r"(r[1]), "=r"(r[2]), "=r"(r[3]) : "r"(addr));
}
__device__ __forceinline__ void mma16816(float (&c)[4], const uint32_t (&a)[4],
                                         const uint32_t* b) {
    asm volatile(
        "mma.sync.aligned.m16n8k16.row.col.f32.bf16.bf16.f32 "
        "{%0,%1,%2,%3}, {%4,%5,%6,%7}, {%8,%9}, {%0,%1,%2,%3};"
        : "+f"(c[0]), "+f"(c[1]), "+f"(c[2]), "+f"(c[3])
        : "r"(a[0]), "r"(a[1]), "r"(a[2]), "r"(a[3]), "r"(b[0]), "r"(b[1]));
}
__device__ __forceinline__ void mma_f16(float (&c)[4], const uint32_t (&a)[4],
                                        const uint32_t* b) {
    asm volatile(
        "mma.sync.aligned.m16n8k16.row.col.f32.f16.f16.f32 "
        "{%0,%1,%2,%3}, {%4,%5,%6,%7}, {%8,%9}, {%0,%1,%2,%3};"
        : "+f"(c[0]), "+f"(c[1]), "+f"(c[2]), "+f"(c[3])
        : "r"(a[0]), "r"(a[1]), "r"(a[2]), "r"(a[3]), "r"(b[0]), "r"(b[1]));
}
__device__ __forceinline__ void split2h(float v, __half& hi, __half& lo) {
    hi = __float2half_rn(v);
    lo = __float2half_rn(v - __half2float(hi));
}

// ===========================================================================
// Conversion kernels
// ===========================================================================
__global__ __launch_bounds__(256) void cvt_adj_k(const float* __restrict__ a)
{
    const int i = blockIdx.x * 256 + threadIdx.x;
    float4 v = ld4(a + (size_t)i * 4);
    *reinterpret_cast<__nv_bfloat162*>(g_adjb + (size_t)i * 4)     =
        __floats2bfloat162_rn(v.x, v.y);
    *reinterpret_cast<__nv_bfloat162*>(g_adjb + (size_t)i * 4 + 2) =
        __floats2bfloat162_rn(v.z, v.w);
}

__global__ __launch_bounds__(256) void cvt_xh_k(const float* __restrict__ x,
                                                const float* __restrict__ hz)
{
    const int i = blockIdx.x * 256 + threadIdx.x;
    const bool isHz = i >= 2097152;
    const int j = isHz ? i - 2097152 : i;
    const int row = j >> 5;
    const int c4  = (j & 31) * 4;
    float4 v = ld4((isHz ? hz : x) + (size_t)row * 128 + c4);
    const size_t o = (size_t)row * 256 + (isHz ? 128 : 0) + c4;
    *reinterpret_cast<__half2*>(g_xh + o)     = __floats2half2_rn(v.x, v.y);
    *reinterpret_cast<__half2*>(g_xh + o + 2) = __floats2half2_rn(v.z, v.w);
}

__global__ __launch_bounds__(256) void cvt_w_k(const float* __restrict__ Wa,
                                               const float* __restrict__ Wb,
                                               const float* __restrict__ W1,
                                               const float* __restrict__ W2)
{
    const int i = blockIdx.x * 256 + threadIdx.x;
    if (i < 65536) {
        const int n = i >> 8, k = i & 255;
        __half hi, lo;
        split2h(Wa[k * 256 + n], hi, lo);
        g_WaT_h[i] = hi; g_WaT_l[i] = lo;
    } else if (i < 65536 + 32768) {
        const int j = i - 65536;
        const int n = j >> 8, k = j & 255;
        __half hi, lo;
        split2h(Wb[k * 128 + n], hi, lo);
        g_WbT_h[j] = hi; g_WbT_l[j] = lo;
    } else if (i < 65536 + 32768 + 8192) {
        const int j = i - 65536 - 32768;
        const int dh = j >> 7, k = j & 127;
        g_W1Tb[j] = __float2bfloat16(W1[k * 128 + dh]);
    } else if (i < 65536 + 32768 + 16384) {
        const int j = i - 65536 - 32768 - 8192;
        const int dh = j >> 7, k = j & 127;
        g_W2Tb[j] = __float2bfloat16(W2[k * 128 + 64 + dh]);
    }
}

// ===========================================================================
// MLP GEMM (fp16 2-term split): C = act(A @ (Wh + Wl)^T + bias)
//   A single fp16; weights split hi/lo fp16. Dropped term al*b ~ 2^-12 rel.
// CTA 128x128, K=256 in 8 chunks of 32 (64B rows, SW64 swizzle),
// 3-stage cp.async (stage = 3 x 8KB = 24KB -> 72KB total), 2 CTAs/SM.
//   MODE 1: relu -> g_af (fp16).   MODE 2: tanh -> g_h (fp32) + g_hb (bf16).
// ===========================================================================
static constexpr int MLP_STG_B = 24576;
static constexpr int MLP_SMEM  = 3 * MLP_STG_B;   // 73728
static constexpr int MLP_NK    = 8;               // 256 / 32

template <int MODE>
__global__ __launch_bounds__(256, 2) void mlp_mma_k(
    const __half* __restrict__ A,
    const __half* __restrict__ Bh, const __half* __restrict__ Bl,
    const float* __restrict__ bias)
{
    extern __shared__ char smem[];
    const uint32_t sb = s2u(smem);
    const int tid  = threadIdx.x;
    const int lane = tid & 31;
    const int warp = tid >> 5;
    const int wm   = warp & 1;       // 2 warps M (64 each)
    const int wn   = warp >> 1;      // 4 warps N (32 each)
    const int bx = blockIdx.x;
    const int by = blockIdx.y;

    float acc[4][4][4];
#pragma unroll
    for (int i = 0; i < 4; i++)
#pragma unroll
        for (int j = 0; j < 4; j++)
#pragma unroll
            for (int v = 0; v < 4; v++) acc[i][j][v] = 0.0f;

    const int ldRow  = tid >> 1;         // 0..127
    const int ldHalf = tid & 1;          // 2 x 16B chunks each

    auto issue = [&](int c, int s) {
        const uint32_t st = sb + s * MLP_STG_B;
        const size_t aOff = (size_t)(by * 128 + ldRow) * 256 + c * 32;
        const size_t bOff = (size_t)(bx * 128 + ldRow) * 256 + c * 32;
#pragma unroll
        for (int j = 0; j < 2; j++) {
            const int chunk = ldHalf * 2 + j;
            const uint32_t so = swz64((uint32_t)(ldRow * 64 + chunk * 16));
            const int e = chunk * 8;
            cp16(st + so,          A  + aOff + e);
            cp16(st + 8192 + so,   Bh + bOff + e);
            cp16(st + 16384 + so,  Bl + bOff + e);
        }
    };

    auto compute = [&](int s) {
        const uint32_t st = sb + s * MLP_STG_B;
#pragma unroll
        for (int ks = 0; ks < 2; ks++) {
            const int k0b = ks * 32;
            uint32_t ah[4][4];
#pragma unroll
            for (int mt = 0; mt < 4; mt++) {
                const int row = wm * 64 + mt * 16 + (lane & 15);
                const uint32_t o = swz64((uint32_t)(row * 64 + k0b + ((lane >> 4) << 4)));
                ldsm4(ah[mt], st + o);
            }
#pragma unroll
            for (int p = 0; p < 2; p++) {
                uint32_t bh[4], bl[4];
                const int row = wn * 32 + p * 16 + (lane & 7) + ((lane >> 4) << 3);
                const uint32_t o = swz64((uint32_t)(row * 64 + k0b + (((lane >> 3) & 1) << 4)));
                ldsm4(bh, st + 8192 + o);
                ldsm4(bl, st + 16384 + o);
#pragma unroll
                for (int mt = 0; mt < 4; mt++)
#pragma unroll
                    for (int sub = 0; sub < 2; sub++) {
                        const int nt = p * 2 + sub;
                        mma_f16(acc[mt][nt], ah[mt], &bh[sub * 2]);
                        mma_f16(acc[mt][nt], ah[mt], &bl[sub * 2]);
                    }
            }
        }
    };

    issue(0, 0);
    asm volatile("cp.async.commit_group;" ::: "memory");
    issue(1, 1);
    asm volatile("cp.async.commit_group;" ::: "memory");
    for (int kt = 0; kt < MLP_NK; kt++) {
        asm volatile("cp.async.wait_group 1;" ::: "memory");
        __syncthreads();
        compute(kt % 3);
        if (kt + 2 < MLP_NK) issue(kt + 2, (kt + 2) % 3);
        asm volatile("cp.async.commit_group;" ::: "memory");
    }

#pragma unroll
    for (int mt = 0; mt < 4; mt++) {
        const int row0 = by * 128 + wm * 64 + mt * 16 + (lane >> 2);
#pragma unroll
        for (int nt = 0; nt < 4; nt++) {
            const int col = bx * 128 + wn * 32 + nt * 8 + 2 * (lane & 3);
            const float b0 = bias[col], b1 = bias[col + 1];
#pragma unroll
            for (int r = 0; r < 2; r++) {
                const int row = row0 + r * 8;
                float v0 = acc[mt][nt][2 * r + 0] + b0;
                float v1 = acc[mt][nt][2 * r + 1] + b1;
                if (MODE == 1) {
                    v0 = fmaxf(v0, 0.0f);
                    v1 = fmaxf(v1, 0.0f);
                    const size_t o = (size_t)row * 256 + col;
                    *reinterpret_cast<__half2*>(g_af + o) = __floats2half2_rn(v0, v1);
                } else {
                    v0 = tanhf(v0);
                    v1 = tanhf(v1);
                    const size_t o = (size_t)row * 128 + col;
                    *reinterpret_cast<float2*>(g_h + o) = make_float2(v0, v1);
                    *reinterpret_cast<__nv_bfloat162*>(g_hb + o) =
                        __floats2bfloat162_rn(v0, v1);
                }
            }
        }
    }
}

// ===========================================================================
// gproj (bf16 mma): g = hb @ WTb^T, bf16 output transposed into gT.
// CTA 128 rows x 64 cols, K=128. 2 CTAs/SM.
// ===========================================================================
static constexpr int GP_SMEM = 49152 + 128 * 68 * 2;

__global__ __launch_bounds__(256, 2) void gproj_k(
    const __nv_bfloat16* __restrict__ WTb, __nv_bfloat16* __restrict__ gT)
{
    extern __shared__ char smem[];
    const uint32_t sb = s2u(smem);
    unsigned short* Ts = reinterpret_cast<unsigned short*>(smem + 49152);
    const int tid  = threadIdx.x;
    const int lane = tid & 31;
    const int warp = tid >> 5;
    const int wm   = warp & 3;
    const int wn   = warp >> 2;
    const int by = blockIdx.y;

    {
        const int r = tid >> 1, half = tid & 1;
        const size_t rowOff = (size_t)(by * 128 + r) * 128;
#pragma unroll
        for (int c = 0; c < 2; c++)
#pragma unroll
            for (int j = 0; j < 4; j++) {
                const uint32_t so = swz((uint32_t)(r * 128 + (half * 4 + j) * 16));
                cp16(sb + c * 16384 + so, g_hb + rowOff + c * 64 + (half * 4 + j) * 8);
            }
    }
    {
        const int r = tid >> 2, q = tid & 3;
#pragma unroll
        for (int c = 0; c < 2; c++)
#pragma unroll
            for (int j = 0; j < 2; j++) {
                const uint32_t so = swz((uint32_t)(r * 128 + (q * 2 + j) * 16));
                cp16(sb + 32768 + c * 8192 + so,
                     WTb + (size_t)r * 128 + c * 64 + (q * 2 + j) * 8);
            }
    }
    asm volatile("cp.async.commit_group;" ::: "memory");
    asm volatile("cp.async.wait_group 0;" ::: "memory");
    __syncthreads();

    float acc[2][4][4];
#pragma unroll
    for (int i = 0; i < 2; i++)
#pragma unroll
        for (int j = 0; j < 4; j++)
#pragma unroll
            for (int v = 0; v < 4; v++) acc[i][j][v] = 0.0f;

#pragma unroll
    for (int c = 0; c < 2; c++) {
        const uint32_t aB = sb + c * 16384;
        const uint32_t bB = sb + 32768 + c * 8192;
#pragma unroll
        for (int ks = 0; ks < 4; ks++) {
            const int k0b = ks * 32;
            uint32_t af[2][4], bf[2][4];
#pragma unroll
            for (int mt = 0; mt < 2; mt++) {
                const int row = wm * 32 + mt * 16 + (lane & 15);
                ldsm4(af[mt], aB + swz((uint32_t)(row * 128 + k0b + ((lane >> 4) << 4))));
            }
#pragma unroll
            for (int p = 0; p < 2; p++) {
                const int row = wn * 32 + p * 16 + (lane & 7) + ((lane >> 4) << 3);
                ldsm4(bf[p], bB + swz((uint32_t)(row * 128 + k0b + (((lane >> 3) & 1) << 4))));
            }
#pragma unroll
            for (int mt = 0; mt < 2; mt++)
#pragma unroll
                for (int nt = 0; nt < 4; nt++)
                    mma16816(acc[mt][nt], af[mt], &bf[nt >> 1][(nt & 1) * 2]);
        }
    }
    __syncthreads();

#pragma unroll
    for (int mt = 0; mt < 2; mt++) {
        const int row0 = wm * 32 + mt * 16 + (lane >> 2);
#pragma unroll
        for (int nt = 0; nt < 4; nt++) {
            const int col = wn * 32 + nt * 8 + 2 * (lane & 3);
#pragma unroll
            for (int r = 0; r < 2; r++) {
                const int row = row0 + r * 8;
                __nv_bfloat16 b0 = __float2bfloat16(acc[mt][nt][2 * r + 0]);
                __nv_bfloat16 b1 = __float2bfloat16(acc[mt][nt][2 * r + 1]);
                Ts[row * 68 + col]     = *reinterpret_cast<unsigned short*>(&b0);
                Ts[row * 68 + col + 1] = *reinterpret_cast<unsigned short*>(&b1);
            }
        }
    }
    __syncthreads();

    const int colp = tid & 63;
    const int seg  = tid >> 6;
    const int b    = by >> 4;
    const int n0   = (by & 15) * 128;
    __nv_bfloat16* dst = gT + (size_t)(b * 64 + colp) * N_ + n0 + seg * 32;
#pragma unroll
    for (int q = 0; q < 4; q++) {
        const int r0 = seg * 32 + q * 8;
        uint32_t w[4];
#pragma unroll
        for (int p = 0; p < 4; p++) {
            uint32_t lo = Ts[(r0 + 2 * p) * 68 + colp];
            uint32_t hi = Ts[(r0 + 2 * p + 1) * 68 + colp];
            w[p] = lo | (hi << 16);
        }
        *reinterpret_cast<uint4*>(dst + q * 8) = make_uint4(w[0], w[1], w[2], w[3]);
    }
}

// ===========================================================================
// adj GEMM (bf16 mma) + fused half-update epilogue.
// CTA 128x128, BK=64, 3-stage cp.async (96 KB), 2 CTAs/SM.
// WOUT = write d_out (last iteration only); WH = write h/hb (not last launch).
// ===========================================================================
static constexpr int AJ_STAGES  = 3;
static constexpr int AJ_NK      = N_ / 64;         // 32
static constexpr int AJ_TILE    = 16384;
static constexpr int AJ_STAGE_B = 2 * AJ_TILE;
static constexpr int ADJ_SMEM   = AJ_STAGES * AJ_STAGE_B;   // 96 KB

template <int HID, bool WOUT, bool WH>
__global__ __launch_bounds__(256, 2) void adj_mma_k(
    float* __restrict__ out, const float* __restrict__ eps)
{
    extern __shared__ char smem[];
    const uint32_t sb = s2u(smem);
    const int tid  = threadIdx.x;
    const int lane = tid & 31;
    const int warp = tid >> 5;
    const int wm   = warp & 1;
    const int wn   = warp >> 1;
    const int bx = blockIdx.x;
    const int by = blockIdx.y;

    const char* aSrc = (const char*)(g_adjb + (size_t)(by * 128) * N_);
    const char* bSrc = (const char*)(g_gT   + (size_t)(bx * 128) * N_);

    float acc[4][4][4];
#pragma unroll
    for (int i = 0; i < 4; i++)
#pragma unroll
        for (int j = 0; j < 4; j++)
#pragma unroll
            for (int v = 0; v < 4; v++) acc[i][j][v] = 0.0f;

    const int ldRow = tid >> 3;
    const int ldCol = tid & 7;

    auto issue = [&](int kt, int s) {
        const uint32_t aB = sb + s * AJ_STAGE_B;
        const uint32_t bB = aB + AJ_TILE;
#pragma unroll
        for (int i = 0; i < 4; i++) {
            const int row = ldRow + 32 * i;
            const uint32_t so = swz((uint32_t)(row * 128 + ldCol * 16));
            const size_t gsrc = (size_t)row * (N_ * 2) + kt * 128 + ldCol * 16;
            cp16(aB + so, aSrc + gsrc);
            cp16(bB + so, bSrc + gsrc);
        }
    };

    auto compute = [&](int s) {
        const uint32_t aB = sb + s * AJ_STAGE_B;
        const uint32_t bB = aB + AJ_TILE;
#pragma unroll
        for (int ks = 0; ks < 4; ks++) {
            const int k0b = ks * 32;
            uint32_t af[4][4], bf[2][4];
#pragma unroll
            for (int mt = 0; mt < 4; mt++) {
                const int row = wm * 64 + mt * 16 + (lane & 15);
                ldsm4(af[mt], aB + swz((uint32_t)(row * 128 + k0b + ((lane >> 4) << 4))));
            }
#pragma unroll
            for (int p = 0; p < 2; p++) {
                const int row = wn * 32 + p * 16 + (lane & 7) + ((lane >> 4) << 3);
                ldsm4(bf[p], bB + swz((uint32_t)(row * 128 + k0b + (((lane >> 3) & 1) << 4))));
            }
#pragma unroll
            for (int mt = 0; mt < 4; mt++)
#pragma unroll
                for (int nt = 0; nt < 4; nt++)
                    mma16816(acc[mt][nt], af[mt], &bf[nt >> 1][(nt & 1) * 2]);
        }
    };

    issue(0, 0);
    asm volatile("cp.async.commit_group;" ::: "memory");
    issue(1, 1);
    asm volatile("cp.async.commit_group;" ::: "memory");
    for (int kt = 0; kt < AJ_NK; kt++) {
        asm volatile("cp.async.wait_group 1;" ::: "memory");
        __syncthreads();
        compute(kt % 3);
        const int f = kt + 2;
        if (f < AJ_NK) issue(f, f % 3);
        asm volatile("cp.async.commit_group;" ::: "memory");
    }

    // fused epilogue
#pragma unroll
    for (int mt = 0; mt < 4; mt++) {
        const int node0 = by * 128 + wm * 64 + mt * 16 + (lane >> 2);
#pragma unroll
        for (int nt = 0; nt < 4; nt++) {
            const int col = bx * 128 + wn * 32 + nt * 8 + 2 * (lane & 3);
            const int b  = col >> 6;
            const int dh = col & 63;
#pragma unroll
            for (int r = 0; r < 2; r++) {
                const int node = node0 + r * 8;
                const float t0 = acc[mt][nt][2 * r + 0];
                const float t1 = acc[mt][nt][2 * r + 1];
                const size_t bn = (size_t)b * N_ + node;
                const size_t hi = bn * D_ + HID * HALF_ + dh;
                float2 hv = *reinterpret_cast<const float2*>(g_h + hi);
                if (HID == 0) {
                    hv.x += DT_ * tanh_fast(t0);
                    hv.y += DT_ * tanh_fast(t1);
                } else {
                    float2 ev = *reinterpret_cast<const float2*>(eps + bn * HALF_ + dh);
                    ev.x = fminf(fmaxf(ev.x, 0.0f), 0.1f);
                    ev.y = fminf(fmaxf(ev.y, 0.0f), 0.1f);
                    hv.x = ev.x * (hv.x + DT_ * tanh_fast(t0));
                    hv.y = ev.y * (hv.y + DT_ * tanh_fast(t1));
                }
                if (WH) {
                    *reinterpret_cast<float2*>(g_h + hi) = hv;
                    *reinterpret_cast<__nv_bfloat162*>(g_hb + hi) =
                        __floats2bfloat162_rn(hv.x, hv.y);
                }
                if (WOUT)
                    *reinterpret_cast<float2*>(out + hi) = hv;
            }
        }
    }
}

// ===========================================================================
extern "C" void kernel_launch(void* const* d_in, const int* /*in_sizes*/,
                              int /*n_in*/, void* d_out, int /*out_size*/)
{
    const float* x   = (const float*)d_in[0];
    const float* hz  = (const float*)d_in[1];
    const float* adj = (const float*)d_in[2];
    const float* W1  = (const float*)d_in[3];
    const float* W2  = (const float*)d_in[4];
    const float* Wa  = (const float*)d_in[5];
    const float* ba  = (const float*)d_in[6];
    const float* Wb  = (const float*)d_in[7];
    const float* bb  = (const float*)d_in[8];
    const float* eps = (const float*)d_in[9];
    float* out = (float*)d_out;

    __half *xh_p, *af_p, *WaT_h, *WaT_l, *WbT_h, *WbT_l;
    __nv_bfloat16 *W1Tb, *W2Tb, *gT_p;
    cudaGetSymbolAddress((void**)&xh_p, g_xh);
    cudaGetSymbolAddress((void**)&af_p, g_af);
    cudaGetSymbolAddress((void**)&WaT_h, g_WaT_h);
    cudaGetSymbolAddress((void**)&WaT_l, g_WaT_l);
    cudaGetSymbolAddress((void**)&WbT_h, g_WbT_h);
    cudaGetSymbolAddress((void**)&WbT_l, g_WbT_l);
    cudaGetSymbolAddress((void**)&W1Tb, g_W1Tb);
    cudaGetSymbolAddress((void**)&W2Tb, g_W2Tb);
    cudaGetSymbolAddress((void**)&gT_p, g_gT);

    cudaFuncSetAttribute(mlp_mma_k<1>,
                         cudaFuncAttributeMaxDynamicSharedMemorySize, MLP_SMEM);
    cudaFuncSetAttribute(mlp_mma_k<2>,
                         cudaFuncAttributeMaxDynamicSharedMemorySize, MLP_SMEM);
    cudaFuncSetAttribute(gproj_k,
                         cudaFuncAttributeMaxDynamicSharedMemorySize, GP_SMEM);
    cudaFuncSetAttribute((const void*)adj_mma_k<0, false, true>,
                         cudaFuncAttributeMaxDynamicSharedMemorySize, ADJ_SMEM);
    cudaFuncSetAttribute((const void*)adj_mma_k<1, false, true>,
                         cudaFuncAttributeMaxDynamicSharedMemorySize, ADJ_SMEM);
    cudaFuncSetAttribute((const void*)adj_mma_k<0, true, true>,
                         cudaFuncAttributeMaxDynamicSharedMemorySize, ADJ_SMEM);
    cudaFuncSetAttribute((const void*)adj_mma_k<1, true, false>,
                         cudaFuncAttributeMaxDynamicSharedMemorySize, ADJ_SMEM);

    const dim3 blk(256);
    const dim3 adjGrid(N_ / 128, N_ / 128);

    cvt_adj_k<<<(N_ * N_) / 1024, blk>>>(adj);
    cvt_xh_k<<<16384, blk>>>(x, hz);
    cvt_w_k<<<448, blk>>>(Wa, Wb, W1, W2);

    mlp_mma_k<1><<<dim3(2, M_ROWS / 128), blk, MLP_SMEM>>>(xh_p, WaT_h, WaT_l, ba);
    mlp_mma_k<2><<<dim3(1, M_ROWS / 128), blk, MLP_SMEM>>>(af_p, WbT_h, WbT_l, bb);

    // iteration 0: out writes skipped (overwritten by iteration 1)
    gproj_k<<<dim3(1, M_ROWS / 128), blk, GP_SMEM>>>(W1Tb, gT_p);
    adj_mma_k<0, false, true><<<adjGrid, blk, ADJ_SMEM>>>(out, eps);
    gproj_k<<<dim3(1, M_ROWS / 128), blk, GP_SMEM>>>(W2Tb, gT_p);
    adj_mma_k<1, false, true><<<adjGrid, blk, ADJ_SMEM>>>(out, eps);

    // iteration 1: write out; final launch skips dead h/hb stores
    gproj_k<<<dim3(1, M_ROWS / 128), blk, GP_SMEM>>>(W1Tb, gT_p);
    adj_mma_k<0, true, true><<<adjGrid, blk, ADJ_SMEM>>>(out, eps);
    gproj_k<<<dim3(1, M_ROWS / 128), blk, GP_SMEM>>>(W2Tb, gT_p);
    adj_mma_k<1, true, false><<<adjGrid, blk, ADJ_SMEM>>>(out, eps);
}

// round 12
// speedup vs baseline: 2.3993x; 1.0647x over previous
#include <cuda_runtime.h>
#include <cuda_bf16.h>
#include <cuda_fp16.h>
#include <math.h>
#include <stdint.h>

// Problem constants
static constexpr int B_    = 32;
static constexpr int N_    = 2048;
static constexpr int D_    = 128;
static constexpr int HALF_ = 64;
static constexpr float DT_ = 0.01f;
static constexpr int M_ROWS = B_ * N_;   // 65536

// Scratch (static device globals)
__device__ float         g_h  [M_ROWS * D_];      // h fp32 [B][N][D]
__device__ __nv_bfloat16 g_hb [M_ROWS * D_];      // bf16 mirror of h
__device__ __nv_bfloat16 g_adjb[N_ * N_];         // adj bf16
__device__ __nv_bfloat16 g_gT [2 * N_ * N_];      // gT [b*128+d][node] (4096x2048)
__device__ __half        g_xh [M_ROWS * 256];     // concat(x,hz) fp16
__device__ __half        g_af [M_ROWS * 256];     // relu hidden fp16
__device__ __half        g_WaT_h[256 * 256], g_WaT_l[256 * 256];
__device__ __half        g_WbT_h[128 * 256], g_WbT_l[128 * 256];
__device__ __nv_bfloat16 g_WcT[128 * 128];        // [d][k]: d<64->W1, d>=64->W2

__device__ __forceinline__ float4 ld4(const float* p) {
    return *reinterpret_cast<const float4*>(p);
}
__device__ __forceinline__ uint32_t s2u(const void* p) {
    uint32_t r;
    asm("{ .reg .u64 t; cvta.to.shared.u64 t, %1; cvt.u32.u64 %0, t; }"
        : "=r"(r) : "l"(p));
    return r;
}
__device__ __forceinline__ void cp16(uint32_t d, const void* s) {
    asm volatile("cp.async.cg.shared.global [%0], [%1], 16;" :: "r"(d), "l"(s) : "memory");
}
__device__ __forceinline__ uint32_t swz(uint32_t o)   { return o ^ ((o >> 3) & 0x70); }
__device__ __forceinline__ uint32_t swz64(uint32_t o) { return o ^ ((o >> 3) & 0x30); }
__device__ __forceinline__ float tanh_fast(float x) {
    float y;
    asm("tanh.approx.f32 %0, %1;" : "=f"(y) : "f"(x));
    return y;
}
__device__ __forceinline__ void ldsm4(uint32_t (&r)[4], uint32_t addr) {
    asm volatile("ldmatrix.sync.aligned.m8n8.x4.shared.b16 {%0,%1,%2,%3}, [%4];"
                 : "=r"(r[0]), "=r"(r[1]), "=r"(r[2]), "=r"(r[3]) : "r"(addr));
}
__device__ __forceinline__ void mma16816(float (&c)[4], const uint32_t (&a)[4],
                                         const uint32_t* b) {
    asm volatile(
        "mma.sync.aligned.m16n8k16.row.col.f32.bf16.bf16.f32 "
        "{%0,%1,%2,%3}, {%4,%5,%6,%7}, {%8,%9}, {%0,%1,%2,%3};"
        : "+f"(c[0]), "+f"(c[1]), "+f"(c[2]), "+f"(c[3])
        : "r"(a[0]), "r"(a[1]), "r"(a[2]), "r"(a[3]), "r"(b[0]), "r"(b[1]));
}
__device__ __forceinline__ void mma_f16(float (&c)[4], const uint32_t (&a)[4],
                                        const uint32_t* b) {
    asm volatile(
        "mma.sync.aligned.m16n8k16.row.col.f32.f16.f16.f32 "
        "{%0,%1,%2,%3}, {%4,%5,%6,%7}, {%8,%9}, {%0,%1,%2,%3};"
        : "+f"(c[0]), "+f"(c[1]), "+f"(c[2]), "+f"(c[3])
        : "r"(a[0]), "r"(a[1]), "r"(a[2]), "r"(a[3]), "r"(b[0]), "r"(b[1]));
}
__device__ __forceinline__ void split2h(float v, __half& hi, __half& lo) {
    hi = __float2half_rn(v);
    lo = __float2half_rn(v - __half2float(hi));
}

// ===========================================================================
// Conversion kernels
// ===========================================================================
__global__ __launch_bounds__(256) void cvt_adj_k(const float* __restrict__ a)
{
    const int i = blockIdx.x * 256 + threadIdx.x;
    float4 v = ld4(a + (size_t)i * 4);
    *reinterpret_cast<__nv_bfloat162*>(g_adjb + (size_t)i * 4)     =
        __floats2bfloat162_rn(v.x, v.y);
    *reinterpret_cast<__nv_bfloat162*>(g_adjb + (size_t)i * 4 + 2) =
        __floats2bfloat162_rn(v.z, v.w);
}

__global__ __launch_bounds__(256) void cvt_xh_k(const float* __restrict__ x,
                                                const float* __restrict__ hz)
{
    const int i = blockIdx.x * 256 + threadIdx.x;
    const bool isHz = i >= 2097152;
    const int j = isHz ? i - 2097152 : i;
    const int row = j >> 5;
    const int c4  = (j & 31) * 4;
    float4 v = ld4((isHz ? hz : x) + (size_t)row * 128 + c4);
    const size_t o = (size_t)row * 256 + (isHz ? 128 : 0) + c4;
    *reinterpret_cast<__half2*>(g_xh + o)     = __floats2half2_rn(v.x, v.y);
    *reinterpret_cast<__half2*>(g_xh + o + 2) = __floats2half2_rn(v.z, v.w);
}

__global__ __launch_bounds__(256) void cvt_w_k(const float* __restrict__ Wa,
                                               const float* __restrict__ Wb,
                                               const float* __restrict__ W1,
                                               const float* __restrict__ W2)
{
    const int i = blockIdx.x * 256 + threadIdx.x;
    if (i < 65536) {
        const int n = i >> 8, k = i & 255;
        __half hi, lo;
        split2h(Wa[k * 256 + n], hi, lo);
        g_WaT_h[i] = hi; g_WaT_l[i] = lo;
    } else if (i < 65536 + 32768) {
        const int j = i - 65536;
        const int n = j >> 8, k = j & 255;
        __half hi, lo;
        split2h(Wb[k * 128 + n], hi, lo);
        g_WbT_h[j] = hi; g_WbT_l[j] = lo;
    } else if (i < 65536 + 32768 + 16384) {
        const int j = i - 98304;
        const int d = j >> 7, k = j & 127;
        const float w = (d < 64) ? W1[k * 128 + d] : W2[k * 128 + d];
        g_WcT[j] = __float2bfloat16(w);
    }
}

// ===========================================================================
// MLP GEMM (fp16 2-term split) — unchanged from R11.
// ===========================================================================
static constexpr int MLP_STG_B = 24576;
static constexpr int MLP_SMEM  = 3 * MLP_STG_B;   // 73728
static constexpr int MLP_NK    = 8;

template <int MODE>
__global__ __launch_bounds__(256, 2) void mlp_mma_k(
    const __half* __restrict__ A,
    const __half* __restrict__ Bh, const __half* __restrict__ Bl,
    const float* __restrict__ bias)
{
    extern __shared__ char smem[];
    const uint32_t sb = s2u(smem);
    const int tid  = threadIdx.x;
    const int lane = tid & 31;
    const int warp = tid >> 5;
    const int wm   = warp & 1;
    const int wn   = warp >> 1;
    const int bx = blockIdx.x;
    const int by = blockIdx.y;

    float acc[4][4][4];
#pragma unroll
    for (int i = 0; i < 4; i++)
#pragma unroll
        for (int j = 0; j < 4; j++)
#pragma unroll
            for (int v = 0; v < 4; v++) acc[i][j][v] = 0.0f;

    const int ldRow  = tid >> 1;
    const int ldHalf = tid & 1;

    auto issue = [&](int c, int s) {
        const uint32_t st = sb + s * MLP_STG_B;
        const size_t aOff = (size_t)(by * 128 + ldRow) * 256 + c * 32;
        const size_t bOff = (size_t)(bx * 128 + ldRow) * 256 + c * 32;
#pragma unroll
        for (int j = 0; j < 2; j++) {
            const int chunk = ldHalf * 2 + j;
            const uint32_t so = swz64((uint32_t)(ldRow * 64 + chunk * 16));
            const int e = chunk * 8;
            cp16(st + so,          A  + aOff + e);
            cp16(st + 8192 + so,   Bh + bOff + e);
            cp16(st + 16384 + so,  Bl + bOff + e);
        }
    };

    auto compute = [&](int s) {
        const uint32_t st = sb + s * MLP_STG_B;
#pragma unroll
        for (int ks = 0; ks < 2; ks++) {
            const int k0b = ks * 32;
            uint32_t ah[4][4];
#pragma unroll
            for (int mt = 0; mt < 4; mt++) {
                const int row = wm * 64 + mt * 16 + (lane & 15);
                const uint32_t o = swz64((uint32_t)(row * 64 + k0b + ((lane >> 4) << 4)));
                ldsm4(ah[mt], st + o);
            }
#pragma unroll
            for (int p = 0; p < 2; p++) {
                uint32_t bh[4], bl[4];
                const int row = wn * 32 + p * 16 + (lane & 7) + ((lane >> 4) << 3);
                const uint32_t o = swz64((uint32_t)(row * 64 + k0b + (((lane >> 3) & 1) << 4)));
                ldsm4(bh, st + 8192 + o);
                ldsm4(bl, st + 16384 + o);
#pragma unroll
                for (int mt = 0; mt < 4; mt++)
#pragma unroll
                    for (int sub = 0; sub < 2; sub++) {
                        const int nt = p * 2 + sub;
                        mma_f16(acc[mt][nt], ah[mt], &bh[sub * 2]);
                        mma_f16(acc[mt][nt], ah[mt], &bl[sub * 2]);
                    }
            }
        }
    };

    issue(0, 0);
    asm volatile("cp.async.commit_group;" ::: "memory");
    issue(1, 1);
    asm volatile("cp.async.commit_group;" ::: "memory");
    for (int kt = 0; kt < MLP_NK; kt++) {
        asm volatile("cp.async.wait_group 1;" ::: "memory");
        __syncthreads();
        compute(kt % 3);
        if (kt + 2 < MLP_NK) issue(kt + 2, (kt + 2) % 3);
        asm volatile("cp.async.commit_group;" ::: "memory");
    }

#pragma unroll
    for (int mt = 0; mt < 4; mt++) {
        const int row0 = by * 128 + wm * 64 + mt * 16 + (lane >> 2);
#pragma unroll
        for (int nt = 0; nt < 4; nt++) {
            const int col = bx * 128 + wn * 32 + nt * 8 + 2 * (lane & 3);
            const float b0 = bias[col], b1 = bias[col + 1];
#pragma unroll
            for (int r = 0; r < 2; r++) {
                const int row = row0 + r * 8;
                float v0 = acc[mt][nt][2 * r + 0] + b0;
                float v1 = acc[mt][nt][2 * r + 1] + b1;
                if (MODE == 1) {
                    v0 = fmaxf(v0, 0.0f);
                    v1 = fmaxf(v1, 0.0f);
                    const size_t o = (size_t)row * 256 + col;
                    *reinterpret_cast<__half2*>(g_af + o) = __floats2half2_rn(v0, v1);
                } else {
                    v0 = tanhf(v0);
                    v1 = tanhf(v1);
                    const size_t o = (size_t)row * 128 + col;
                    *reinterpret_cast<float2*>(g_h + o) = make_float2(v0, v1);
                    *reinterpret_cast<__nv_bfloat162*>(g_hb + o) =
                        __floats2bfloat162_rn(v0, v1);
                }
            }
        }
    }
}

// ===========================================================================
// gproj (bf16 mma, merged): g = hb @ WcT^T (128 output cols), bf16
// transposed into gT[b*128+d][node]. CTA 128 rows x 128 cols, K=128.
// 8 warps: wm = warp&1 (M 2x64), wn = warp>>1 (N 4x32). 2 CTAs/SM.
// ===========================================================================
static constexpr int GP_SMEM = 65536 + 128 * 132 * 2;   // 99328

__global__ __launch_bounds__(256, 2) void gproj_k(__nv_bfloat16* __restrict__ gT)
{
    extern __shared__ char smem[];
    const uint32_t sb = s2u(smem);                 // A: [0,32K) B: [32K,64K)
    unsigned short* Ts = reinterpret_cast<unsigned short*>(smem + 65536);
    const int tid  = threadIdx.x;
    const int lane = tid & 31;
    const int warp = tid >> 5;
    const int wm   = warp & 1;
    const int wn   = warp >> 1;
    const int by = blockIdx.y;

    // load A (hb rows) and B (WcT rows): each 128 rows x 2 chunks x 128B
    {
        const int r = tid >> 1, half = tid & 1;
        const size_t aOff = (size_t)(by * 128 + r) * 128;
        const size_t bOff = (size_t)r * 128;
#pragma unroll
        for (int c = 0; c < 2; c++)
#pragma unroll
            for (int j = 0; j < 4; j++) {
                const uint32_t so = swz((uint32_t)(r * 128 + (half * 4 + j) * 16));
                const int e = c * 64 + (half * 4 + j) * 8;
                cp16(sb + c * 16384 + so,         g_hb  + aOff + e);
                cp16(sb + 32768 + c * 16384 + so, g_WcT + bOff + e);
            }
    }
    asm volatile("cp.async.commit_group;" ::: "memory");
    asm volatile("cp.async.wait_group 0;" ::: "memory");
    __syncthreads();

    float acc[4][4][4];
#pragma unroll
    for (int i = 0; i < 4; i++)
#pragma unroll
        for (int j = 0; j < 4; j++)
#pragma unroll
            for (int v = 0; v < 4; v++) acc[i][j][v] = 0.0f;

#pragma unroll
    for (int c = 0; c < 2; c++) {
        const uint32_t aB = sb + c * 16384;
        const uint32_t bB = sb + 32768 + c * 16384;
#pragma unroll
        for (int ks = 0; ks < 4; ks++) {
            const int k0b = ks * 32;
            uint32_t af[4][4], bf[2][4];
#pragma unroll
            for (int mt = 0; mt < 4; mt++) {
                const int row = wm * 64 + mt * 16 + (lane & 15);
                ldsm4(af[mt], aB + swz((uint32_t)(row * 128 + k0b + ((lane >> 4) << 4))));
            }
#pragma unroll
            for (int p = 0; p < 2; p++) {
                const int row = wn * 32 + p * 16 + (lane & 7) + ((lane >> 4) << 3);
                ldsm4(bf[p], bB + swz((uint32_t)(row * 128 + k0b + (((lane >> 3) & 1) << 4))));
            }
#pragma unroll
            for (int mt = 0; mt < 4; mt++)
#pragma unroll
                for (int nt = 0; nt < 4; nt++)
                    mma16816(acc[mt][nt], af[mt], &bf[nt >> 1][(nt & 1) * 2]);
        }
    }
    __syncthreads();

    // stage bf16 then transposed coalesced store
#pragma unroll
    for (int mt = 0; mt < 4; mt++) {
        const int row0 = wm * 64 + mt * 16 + (lane >> 2);
#pragma unroll
        for (int nt = 0; nt < 4; nt++) {
            const int col = wn * 32 + nt * 8 + 2 * (lane & 3);
#pragma unroll
            for (int r = 0; r < 2; r++) {
                const int row = row0 + r * 8;
                __nv_bfloat16 b0 = __float2bfloat16(acc[mt][nt][2 * r + 0]);
                __nv_bfloat16 b1 = __float2bfloat16(acc[mt][nt][2 * r + 1]);
                Ts[row * 132 + col]     = *reinterpret_cast<unsigned short*>(&b0);
                Ts[row * 132 + col + 1] = *reinterpret_cast<unsigned short*>(&b1);
            }
        }
    }
    __syncthreads();

    const int colp = tid & 127;           // output col d (0..127)
    const int seg  = tid >> 7;            // 2 segs x 64 nodes
    const int b    = by >> 4;
    const int n0   = (by & 15) * 128;
    __nv_bfloat16* dst = gT + (size_t)(b * 128 + colp) * N_ + n0 + seg * 64;
#pragma unroll
    for (int q = 0; q < 8; q++) {
        const int r0 = seg * 64 + q * 8;
        uint32_t w[4];
#pragma unroll
        for (int p = 0; p < 4; p++) {
            uint32_t lo = Ts[(r0 + 2 * p) * 132 + colp];
            uint32_t hi = Ts[(r0 + 2 * p + 1) * 132 + colp];
            w[p] = lo | (hi << 16);
        }
        *reinterpret_cast<uint4*>(dst + q * 8) = make_uint4(w[0], w[1], w[2], w[3]);
    }
}

// ===========================================================================
// adj GEMM (bf16 mma, merged) + full h-update epilogue.
// Output cols 0..4095: col' = b*128 + d. Grid (32, 16) -> bx = b.
// Within a CTA the 128 cols are d = 0..127; warp wn<2 -> first-half update,
// wn>=2 -> eps-gated second-half update (pre-update h both halves;
// drops the Dh_f correction in the W2 path, ~3e-5 rel).
// CTA 128x128, BK=64, 3-stage cp.async (96 KB), 2 CTAs/SM.
// ===========================================================================
static constexpr int AJ_STAGES  = 3;
static constexpr int AJ_NK      = N_ / 64;         // 32
static constexpr int AJ_TILE    = 16384;
static constexpr int AJ_STAGE_B = 2 * AJ_TILE;
static constexpr int ADJ_SMEM   = AJ_STAGES * AJ_STAGE_B;   // 96 KB

template <bool WOUT, bool WH>
__global__ __launch_bounds__(256, 2) void adj_mma_k(
    float* __restrict__ out, const float* __restrict__ eps)
{
    extern __shared__ char smem[];
    const uint32_t sb = s2u(smem);
    const int tid  = threadIdx.x;
    const int lane = tid & 31;
    const int warp = tid >> 5;
    const int wm   = warp & 1;
    const int wn   = warp >> 1;
    const int bx = blockIdx.x;      // b (0..31): col' tile = b*128
    const int by = blockIdx.y;      // node tile

    const char* aSrc = (const char*)(g_adjb + (size_t)(by * 128) * N_);
    const char* bSrc = (const char*)(g_gT   + (size_t)(bx * 128) * N_);

    float acc[4][4][4];
#pragma unroll
    for (int i = 0; i < 4; i++)
#pragma unroll
        for (int j = 0; j < 4; j++)
#pragma unroll
            for (int v = 0; v < 4; v++) acc[i][j][v] = 0.0f;

    const int ldRow = tid >> 3;
    const int ldCol = tid & 7;

    auto issue = [&](int kt, int s) {
        const uint32_t aB = sb + s * AJ_STAGE_B;
        const uint32_t bB = aB + AJ_TILE;
#pragma unroll
        for (int i = 0; i < 4; i++) {
            const int row = ldRow + 32 * i;
            const uint32_t so = swz((uint32_t)(row * 128 + ldCol * 16));
            const size_t gsrc = (size_t)row * (N_ * 2) + kt * 128 + ldCol * 16;
            cp16(aB + so, aSrc + gsrc);
            cp16(bB + so, bSrc + gsrc);
        }
    };

    auto compute = [&](int s) {
        const uint32_t aB = sb + s * AJ_STAGE_B;
        const uint32_t bB = aB + AJ_TILE;
#pragma unroll
        for (int ks = 0; ks < 4; ks++) {
            const int k0b = ks * 32;
            uint32_t af[4][4], bf[2][4];
#pragma unroll
            for (int mt = 0; mt < 4; mt++) {
                const int row = wm * 64 + mt * 16 + (lane & 15);
                ldsm4(af[mt], aB + swz((uint32_t)(row * 128 + k0b + ((lane >> 4) << 4))));
            }
#pragma unroll
            for (int p = 0; p < 2; p++) {
                const int row = wn * 32 + p * 16 + (lane & 7) + ((lane >> 4) << 3);
                ldsm4(bf[p], bB + swz((uint32_t)(row * 128 + k0b + (((lane >> 3) & 1) << 4))));
            }
#pragma unroll
            for (int mt = 0; mt < 4; mt++)
#pragma unroll
                for (int nt = 0; nt < 4; nt++)
                    mma16816(acc[mt][nt], af[mt], &bf[nt >> 1][(nt & 1) * 2]);
        }
    };

    issue(0, 0);
    asm volatile("cp.async.commit_group;" ::: "memory");
    issue(1, 1);
    asm volatile("cp.async.commit_group;" ::: "memory");
    for (int kt = 0; kt < AJ_NK; kt++) {
        asm volatile("cp.async.wait_group 1;" ::: "memory");
        __syncthreads();
        compute(kt % 3);
        const int f = kt + 2;
        if (f < AJ_NK) issue(f, f % 3);
        asm volatile("cp.async.commit_group;" ::: "memory");
    }

    // fused epilogue: full h update (both halves in one pass)
    const bool secondHalf = (wn >= 2);
#pragma unroll
    for (int mt = 0; mt < 4; mt++) {
        const int node0 = by * 128 + wm * 64 + mt * 16 + (lane >> 2);
#pragma unroll
        for (int nt = 0; nt < 4; nt++) {
            const int d = wn * 32 + nt * 8 + 2 * (lane & 3);   // 0..127
#pragma unroll
            for (int r = 0; r < 2; r++) {
                const int node = node0 + r * 8;
                const float t0 = acc[mt][nt][2 * r + 0];
                const float t1 = acc[mt][nt][2 * r + 1];
                const size_t bn = (size_t)bx * N_ + node;
                const size_t hi = bn * D_ + d;
                float2 hv = *reinterpret_cast<const float2*>(g_h + hi);
                if (!secondHalf) {
                    hv.x += DT_ * tanh_fast(t0);
                    hv.y += DT_ * tanh_fast(t1);
                } else {
                    float2 ev = *reinterpret_cast<const float2*>(
                        eps + bn * HALF_ + (d - HALF_));
                    ev.x = fminf(fmaxf(ev.x, 0.0f), 0.1f);
                    ev.y = fminf(fmaxf(ev.y, 0.0f), 0.1f);
                    hv.x = ev.x * (hv.x + DT_ * tanh_fast(t0));
                    hv.y = ev.y * (hv.y + DT_ * tanh_fast(t1));
                }
                if (WH) {
                    *reinterpret_cast<float2*>(g_h + hi) = hv;
                    *reinterpret_cast<__nv_bfloat162*>(g_hb + hi) =
                        __floats2bfloat162_rn(hv.x, hv.y);
                }
                if (WOUT)
                    *reinterpret_cast<float2*>(out + hi) = hv;
            }
        }
    }
}

// ===========================================================================
extern "C" void kernel_launch(void* const* d_in, const int* /*in_sizes*/,
                              int /*n_in*/, void* d_out, int /*out_size*/)
{
    const float* x   = (const float*)d_in[0];
    const float* hz  = (const float*)d_in[1];
    const float* adj = (const float*)d_in[2];
    const float* W1  = (const float*)d_in[3];
    const float* W2  = (const float*)d_in[4];
    const float* Wa  = (const float*)d_in[5];
    const float* ba  = (const float*)d_in[6];
    const float* Wb  = (const float*)d_in[7];
    const float* bb  = (const float*)d_in[8];
    const float* eps = (const float*)d_in[9];
    float* out = (float*)d_out;

    __half *xh_p, *af_p, *WaT_h, *WaT_l, *WbT_h, *WbT_l;
    __nv_bfloat16 *gT_p;
    cudaGetSymbolAddress((void**)&xh_p, g_xh);
    cudaGetSymbolAddress((void**)&af_p, g_af);
    cudaGetSymbolAddress((void**)&WaT_h, g_WaT_h);
    cudaGetSymbolAddress((void**)&WaT_l, g_WaT_l);
    cudaGetSymbolAddress((void**)&WbT_h, g_WbT_h);
    cudaGetSymbolAddress((void**)&WbT_l, g_WbT_l);
    cudaGetSymbolAddress((void**)&gT_p, g_gT);

    cudaFuncSetAttribute(mlp_mma_k<1>,
                         cudaFuncAttributeMaxDynamicSharedMemorySize, MLP_SMEM);
    cudaFuncSetAttribute(mlp_mma_k<2>,
                         cudaFuncAttributeMaxDynamicSharedMemorySize, MLP_SMEM);
    cudaFuncSetAttribute(gproj_k,
                         cudaFuncAttributeMaxDynamicSharedMemorySize, GP_SMEM);
    cudaFuncSetAttribute((const void*)adj_mma_k<false, true>,
                         cudaFuncAttributeMaxDynamicSharedMemorySize, ADJ_SMEM);
    cudaFuncSetAttribute((const void*)adj_mma_k<true, false>,
                         cudaFuncAttributeMaxDynamicSharedMemorySize, ADJ_SMEM);

    const dim3 blk(256);
    const dim3 adjGrid(2 * N_ / 128, N_ / 128);   // 32 x 16

    cvt_adj_k<<<(N_ * N_) / 1024, blk>>>(adj);
    cvt_xh_k<<<16384, blk>>>(x, hz);
    cvt_w_k<<<448, blk>>>(Wa, Wb, W1, W2);

    mlp_mma_k<1><<<dim3(2, M_ROWS / 128), blk, MLP_SMEM>>>(xh_p, WaT_h, WaT_l, ba);
    mlp_mma_k<2><<<dim3(1, M_ROWS / 128), blk, MLP_SMEM>>>(af_p, WbT_h, WbT_l, bb);

    // iteration 0: out writes skipped (overwritten by iteration 1)
    gproj_k<<<dim3(1, M_ROWS / 128), blk, GP_SMEM>>>(gT_p);
    adj_mma_k<false, true><<<adjGrid, blk, ADJ_SMEM>>>(out, eps);

    // iteration 1: write out; skip dead h/hb stores
    gproj_k<<<dim3(1, M_ROWS / 128), blk, GP_SMEM>>>(gT_p);
    adj_mma_k<true, false><<<adjGrid, blk, ADJ_SMEM>>>(out, eps);
}